// round 1
// baseline (speedup 1.0000x reference)
#include <cuda_runtime.h>
#include <math.h>
#include <stddef.h>

#define BSZ   4
#define TLEN  2048
#define DIM_  1024
#define NH    16
#define HDIM  64
#define BT    (BSZ * TLEN)        // 8192

// Scratch (device-global; no runtime allocation)
__device__ float g_Q[(size_t)BSZ * NH * TLEN * HDIM];
__device__ float g_K[(size_t)BSZ * NH * TLEN * HDIM];
__device__ float g_V[(size_t)BSZ * NH * TLEN * HDIM];
__device__ float g_O[(size_t)BSZ * NH * TLEN * HDIM];
__device__ float g_Hh[(size_t)BT * DIM_];

// ---------------------------------------------------------------------------
// Kernel 1: QKV projection.  Y[m,e] = sum_d x[m,d] * W[e,d]   (NT GEMM)
// Writes to [B, H, T, HD] layout.  blockIdx.z selects Wq/Wk/Wv.
// Tiles: BM=128, BN=64, BK=16; 256 threads; 8x4 per thread.
// ---------------------------------------------------------------------------
__global__ __launch_bounds__(256) void qkv_kernel(
    const float* __restrict__ x,
    const float* __restrict__ Wq,
    const float* __restrict__ Wk,
    const float* __restrict__ Wv)
{
    constexpr int BM = 128, BN = 64, BK = 16;
    __shared__ __align__(16) float As[BK][BM + 4];
    __shared__ __align__(16) float Bs[BK][BN + 4];

    const int tid = threadIdx.x;
    const int tx = tid & 15, ty = tid >> 4;
    const int m0 = blockIdx.x * BM;
    const int n0 = blockIdx.y * BN;
    const int which = blockIdx.z;
    const float* __restrict__ W = (which == 0) ? Wq : (which == 1 ? Wk : Wv);
    float* __restrict__ outp = (which == 0) ? g_Q : (which == 1 ? g_K : g_V);

    float acc[8][4];
#pragma unroll
    for (int i = 0; i < 8; i++)
#pragma unroll
        for (int j = 0; j < 4; j++) acc[i][j] = 0.0f;

    const int arow = tid >> 2;        // 0..63
    const int akq  = (tid & 3) * 4;   // 0,4,8,12

    for (int k0 = 0; k0 < DIM_; k0 += BK) {
#pragma unroll
        for (int r = 0; r < 2; r++) {
            int row = arow + r * 64;
            float4 v = *(const float4*)(x + (size_t)(m0 + row) * DIM_ + k0 + akq);
            As[akq + 0][row] = v.x; As[akq + 1][row] = v.y;
            As[akq + 2][row] = v.z; As[akq + 3][row] = v.w;
        }
        {
            float4 v = *(const float4*)(W + (size_t)(n0 + arow) * DIM_ + k0 + akq);
            Bs[akq + 0][arow] = v.x; Bs[akq + 1][arow] = v.y;
            Bs[akq + 2][arow] = v.z; Bs[akq + 3][arow] = v.w;
        }
        __syncthreads();
#pragma unroll
        for (int kk = 0; kk < BK; kk++) {
            float a[8], b[4];
            *(float4*)&a[0] = *(const float4*)&As[kk][ty * 8];
            *(float4*)&a[4] = *(const float4*)&As[kk][ty * 8 + 4];
            *(float4*)&b[0] = *(const float4*)&Bs[kk][tx * 4];
#pragma unroll
            for (int i = 0; i < 8; i++)
#pragma unroll
                for (int j = 0; j < 4; j++)
                    acc[i][j] += a[i] * b[j];
        }
        __syncthreads();
    }

    // Epilogue: write to [B,H,T,HD].  BN=64 == HD, so one head per block col.
    const int hh = n0 >> 6;
    const int hd0 = tx * 4;
#pragma unroll
    for (int i = 0; i < 8; i++) {
        int m = m0 + ty * 8 + i;
        int bb = m >> 11;            // / TLEN
        int t  = m & (TLEN - 1);
        float4 v = make_float4(acc[i][0], acc[i][1], acc[i][2], acc[i][3]);
        *(float4*)(outp + (((size_t)(bb * NH + hh)) * TLEN + t) * HDIM + hd0) = v;
    }
}

// ---------------------------------------------------------------------------
// Kernel 2: RoPE on Q and K, in place.  Folds attention scale (1/8) into Q.
// One thread per (b,h,t,j), j in [0,32): handles the (j, j+32) pair.
// ---------------------------------------------------------------------------
__global__ __launch_bounds__(256) void rope_kernel()
{
    int idx = blockIdx.x * 256 + threadIdx.x;    // BSZ*NH*TLEN*32 threads
    int j = idx & 31;
    int bht = idx >> 5;
    int t = bht & (TLEN - 1);
    // inv_freq = 10000^(-j/32) = 2^(-j * log2(10000)/32)
    float ang = (float)t * exp2f(-(float)j * (13.287712379549449f / 32.0f));
    float s, c;
    sincosf(ang, &s, &c);
    size_t base = (size_t)bht * HDIM;

    float q1 = g_Q[base + j], q2 = g_Q[base + j + 32];
    const float scale = 0.125f;   // HD^-0.5
    g_Q[base + j]      = (q1 * c - q2 * s) * scale;
    g_Q[base + j + 32] = (q2 * c + q1 * s) * scale;

    float k1 = g_K[base + j], k2 = g_K[base + j + 32];
    g_K[base + j]      = k1 * c - k2 * s;
    g_K[base + j + 32] = k2 * c + k1 * s;
}

// ---------------------------------------------------------------------------
// Kernel 3: flash attention.  Block = (qtile of 64 rows, one (b,h)).
// 256 threads (16x16), 4x4 scores per thread, online softmax, P via smem.
// ---------------------------------------------------------------------------
__global__ __launch_bounds__(256) void attn_kernel(const int* __restrict__ mask)
{
    extern __shared__ float sm[];
    float* Qs = sm;                  // 64*64
    float* Ks = Qs + 64 * 64;        // 64*65 (pad -> <=2-way conflicts)
    float* Vs = Ks + 64 * 65;        // 64*64
    float* Ps = Vs + 64 * 64;        // 64*64

    const int tid = threadIdx.x;
    const int tx = tid & 15, ty = tid >> 4;
    const int qt = blockIdx.x;
    const int bh = blockIdx.y;
    const int bb = bh >> 4;          // / NH

    const float* __restrict__ Qg = g_Q + ((size_t)bh * TLEN + qt * 64) * HDIM;
    const float* __restrict__ Kg = g_K + (size_t)bh * TLEN * HDIM;
    const float* __restrict__ Vg = g_V + (size_t)bh * TLEN * HDIM;
    const int* __restrict__ mrow = mask + (size_t)bb * TLEN;

    // Load Q tile (coalesced float4)
    {
        int row = tid >> 4;             // 0..15
        int cq  = (tid & 15) * 4;
#pragma unroll
        for (int r = 0; r < 4; r++) {
            int rr = row + r * 16;
            *(float4*)&Qs[rr * 64 + cq] = *(const float4*)(Qg + (size_t)rr * 64 + cq);
        }
    }

    float m_i[4], l_i[4], o[4][4];
#pragma unroll
    for (int i = 0; i < 4; i++) {
        m_i[i] = -1e30f; l_i[i] = 0.0f;
#pragma unroll
        for (int j = 0; j < 4; j++) o[i][j] = 0.0f;
    }

    for (int kt = 0; kt < TLEN / 64; kt++) {
        __syncthreads();   // previous iter's PV reads of Ks/Vs/Ps complete
        {
            int row = tid >> 4;
            int cq  = (tid & 15) * 4;
#pragma unroll
            for (int r = 0; r < 4; r++) {
                int rr = row + r * 16;
                float4 kv = *(const float4*)(Kg + ((size_t)kt * 64 + rr) * 64 + cq);
                Ks[rr * 65 + cq + 0] = kv.x; Ks[rr * 65 + cq + 1] = kv.y;
                Ks[rr * 65 + cq + 2] = kv.z; Ks[rr * 65 + cq + 3] = kv.w;
                *(float4*)&Vs[rr * 64 + cq] =
                    *(const float4*)(Vg + ((size_t)kt * 64 + rr) * 64 + cq);
            }
        }
        __syncthreads();

        // S = (Q*scale) K^T   (64x64, 4x4 per thread)
        float s4[4][4];
#pragma unroll
        for (int i = 0; i < 4; i++)
#pragma unroll
            for (int j = 0; j < 4; j++) s4[i][j] = 0.0f;

#pragma unroll 8
        for (int d = 0; d < 64; d++) {
            float a[4], b[4];
#pragma unroll
            for (int i = 0; i < 4; i++) a[i] = Qs[(ty * 4 + i) * 64 + d];
#pragma unroll
            for (int j = 0; j < 4; j++) b[j] = Ks[(tx * 4 + j) * 65 + d];
#pragma unroll
            for (int i = 0; i < 4; i++)
#pragma unroll
                for (int j = 0; j < 4; j++)
                    s4[i][j] += a[i] * b[j];
        }

        // Additive mask
        float madd[4];
#pragma unroll
        for (int j = 0; j < 4; j++)
            madd[j] = (1.0f - (float)mrow[kt * 64 + tx * 4 + j]) * 1e9f;
#pragma unroll
        for (int i = 0; i < 4; i++)
#pragma unroll
            for (int j = 0; j < 4; j++) s4[i][j] -= madd[j];

        // Online softmax
#pragma unroll
        for (int i = 0; i < 4; i++) {
            float rm = fmaxf(fmaxf(s4[i][0], s4[i][1]), fmaxf(s4[i][2], s4[i][3]));
#pragma unroll
            for (int off = 1; off < 16; off <<= 1)
                rm = fmaxf(rm, __shfl_xor_sync(0xffffffffu, rm, off));
            float mnew = fmaxf(m_i[i], rm);
            float corr = __expf(m_i[i] - mnew);
            float rsum = 0.0f;
#pragma unroll
            for (int j = 0; j < 4; j++) {
                s4[i][j] = __expf(s4[i][j] - mnew);
                rsum += s4[i][j];
            }
#pragma unroll
            for (int off = 1; off < 16; off <<= 1)
                rsum += __shfl_xor_sync(0xffffffffu, rsum, off);
            l_i[i] = l_i[i] * corr + rsum;
            m_i[i] = mnew;
#pragma unroll
            for (int j = 0; j < 4; j++) o[i][j] *= corr;
            // stage P
            *(float4*)&Ps[(ty * 4 + i) * 64 + tx * 4] =
                make_float4(s4[i][0], s4[i][1], s4[i][2], s4[i][3]);
        }
        __syncthreads();

        // O += P @ V
#pragma unroll 8
        for (int k = 0; k < 64; k++) {
            float4 v = *(const float4*)&Vs[k * 64 + tx * 4];
#pragma unroll
            for (int i = 0; i < 4; i++) {
                float p = Ps[(ty * 4 + i) * 64 + k];
                o[i][0] += p * v.x; o[i][1] += p * v.y;
                o[i][2] += p * v.z; o[i][3] += p * v.w;
            }
        }
    }

    // Normalize and write out in [B,H,T,HD]
#pragma unroll
    for (int i = 0; i < 4; i++) {
        float inv = 1.0f / l_i[i];
        float4 r = make_float4(o[i][0] * inv, o[i][1] * inv,
                               o[i][2] * inv, o[i][3] * inv);
        *(float4*)(g_O + ((size_t)bh * TLEN + qt * 64 + ty * 4 + i) * 64 + tx * 4) = r;
    }
}

// ---------------------------------------------------------------------------
// Kernel 4: output projection + residual.  A rows gathered from [B,H,T,HD].
// ---------------------------------------------------------------------------
__global__ __launch_bounds__(256) void oproj_kernel(
    const float* __restrict__ x,
    const float* __restrict__ Wo)
{
    constexpr int BM = 128, BN = 64, BK = 16;
    __shared__ __align__(16) float As[BK][BM + 4];
    __shared__ __align__(16) float Bs[BK][BN + 4];

    const int tid = threadIdx.x;
    const int tx = tid & 15, ty = tid >> 4;
    const int m0 = blockIdx.x * BM;
    const int n0 = blockIdx.y * BN;

    float acc[8][4];
#pragma unroll
    for (int i = 0; i < 8; i++)
#pragma unroll
        for (int j = 0; j < 4; j++) acc[i][j] = 0.0f;

    const int arow = tid >> 2;
    const int akq  = (tid & 3) * 4;

    for (int k0 = 0; k0 < DIM_; k0 += BK) {
#pragma unroll
        for (int r = 0; r < 2; r++) {
            int row = arow + r * 64;
            int m = m0 + row;
            int bb = m >> 11;
            int t  = m & (TLEN - 1);
            int kg = k0 + akq;
            int hh = kg >> 6;
            int hd = kg & 63;
            float4 v = *(const float4*)(g_O +
                (((size_t)(bb * NH + hh)) * TLEN + t) * HDIM + hd);
            As[akq + 0][row] = v.x; As[akq + 1][row] = v.y;
            As[akq + 2][row] = v.z; As[akq + 3][row] = v.w;
        }
        {
            float4 v = *(const float4*)(Wo + (size_t)(n0 + arow) * DIM_ + k0 + akq);
            Bs[akq + 0][arow] = v.x; Bs[akq + 1][arow] = v.y;
            Bs[akq + 2][arow] = v.z; Bs[akq + 3][arow] = v.w;
        }
        __syncthreads();
#pragma unroll
        for (int kk = 0; kk < BK; kk++) {
            float a[8], b[4];
            *(float4*)&a[0] = *(const float4*)&As[kk][ty * 8];
            *(float4*)&a[4] = *(const float4*)&As[kk][ty * 8 + 4];
            *(float4*)&b[0] = *(const float4*)&Bs[kk][tx * 4];
#pragma unroll
            for (int i = 0; i < 8; i++)
#pragma unroll
                for (int j = 0; j < 4; j++)
                    acc[i][j] += a[i] * b[j];
        }
        __syncthreads();
    }

    // Epilogue: h = x + proj
#pragma unroll
    for (int i = 0; i < 8; i++) {
        int m = m0 + ty * 8 + i;
        size_t idx = (size_t)m * DIM_ + n0 + tx * 4;
        float4 xr = *(const float4*)(x + idx);
        *(float4*)(g_Hh + idx) = make_float4(acc[i][0] + xr.x, acc[i][1] + xr.y,
                                             acc[i][2] + xr.z, acc[i][3] + xr.w);
    }
}

// ---------------------------------------------------------------------------
// Kernel 5: LayerNorm per row of h. One CTA (256 threads) per row.
// ---------------------------------------------------------------------------
__global__ __launch_bounds__(256) void ln_kernel(
    const float* __restrict__ gamma,
    const float* __restrict__ beta,
    float* __restrict__ out)
{
    __shared__ float red0[8];
    __shared__ float red1[8];
    const int row = blockIdx.x;
    const int tid = threadIdx.x;
    const float* hr = g_Hh + (size_t)row * DIM_;

    float4 v = *(const float4*)(hr + tid * 4);
    float sum = v.x + v.y + v.z + v.w;
    float sq  = v.x * v.x + v.y * v.y + v.z * v.z + v.w * v.w;
#pragma unroll
    for (int off = 16; off; off >>= 1) {
        sum += __shfl_xor_sync(0xffffffffu, sum, off);
        sq  += __shfl_xor_sync(0xffffffffu, sq, off);
    }
    int wid = tid >> 5, lane = tid & 31;
    if (lane == 0) { red0[wid] = sum; red1[wid] = sq; }
    __syncthreads();

    float tot = 0.0f, totsq = 0.0f;
#pragma unroll
    for (int w = 0; w < 8; w++) { tot += red0[w]; totsq += red1[w]; }

    float mu = tot * (1.0f / DIM_);
    float var = totsq * (1.0f / DIM_) - mu * mu;
    float rs = rsqrtf(var + 1e-5f);

    int e = tid * 4;
    float4 g  = *(const float4*)(gamma + e);
    float4 be = *(const float4*)(beta + e);
    float4 r = make_float4((v.x - mu) * rs * g.x + be.x,
                           (v.y - mu) * rs * g.y + be.y,
                           (v.z - mu) * rs * g.z + be.z,
                           (v.w - mu) * rs * g.w + be.w);
    *(float4*)(out + (size_t)row * DIM_ + e) = r;
}

// ---------------------------------------------------------------------------
extern "C" void kernel_launch(void* const* d_in, const int* in_sizes, int n_in,
                              void* d_out, int out_size)
{
    const float* x     = (const float*)d_in[0];
    const int*   mask  = (const int*)d_in[1];
    const float* Wq    = (const float*)d_in[2];
    const float* Wk    = (const float*)d_in[3];
    const float* Wv    = (const float*)d_in[4];
    const float* Wo    = (const float*)d_in[5];
    const float* gamma = (const float*)d_in[6];
    const float* beta  = (const float*)d_in[7];
    float* out = (float*)d_out;

    const int attn_smem = (64 * 64 * 3 + 64 * 65) * 4;   // 65792 B
    cudaFuncSetAttribute(attn_kernel,
                         cudaFuncAttributeMaxDynamicSharedMemorySize, attn_smem);

    dim3 gq(BT / 128, DIM_ / 64, 3);
    qkv_kernel<<<gq, 256>>>(x, Wq, Wk, Wv);

    rope_kernel<<<(BSZ * NH * TLEN * 32) / 256, 256>>>();

    attn_kernel<<<dim3(TLEN / 64, BSZ * NH), 256, attn_smem>>>(mask);

    oproj_kernel<<<dim3(BT / 128, DIM_ / 64), 256>>>(x, Wo);

    ln_kernel<<<BT, 256>>>(gamma, beta, out);
}

// round 2
// speedup vs baseline: 1.4283x; 1.4283x over previous
#include <cuda_runtime.h>
#include <math.h>
#include <stddef.h>
#include <stdint.h>

#define BSZ   4
#define TLEN  2048
#define DIM_  1024
#define NH    16
#define HDIM  64
#define BT    (BSZ * TLEN)        // 8192

// Scratch (device-global; no runtime allocation)
__device__ float g_Q[(size_t)BSZ * NH * TLEN * HDIM];
__device__ float g_K[(size_t)BSZ * NH * TLEN * HDIM];
__device__ float g_V[(size_t)BSZ * NH * TLEN * HDIM];
__device__ float g_O[(size_t)BSZ * NH * TLEN * HDIM];
__device__ float g_Hh[(size_t)BT * DIM_];

// ---------------------------------------------------------------------------
// tf32 helpers
// ---------------------------------------------------------------------------
__device__ __forceinline__ uint32_t f2tf32(float x) {
    uint32_t r;
    asm("cvt.rna.tf32.f32 %0, %1;" : "=r"(r) : "f"(x));
    return r;
}

__device__ __forceinline__ void mma_tf32(float c[4],
                                         const uint32_t a[4],
                                         const uint32_t b[2]) {
    asm volatile(
        "mma.sync.aligned.m16n8k8.row.col.f32.tf32.tf32.f32 "
        "{%0,%1,%2,%3},{%4,%5,%6,%7},{%8,%9},{%0,%1,%2,%3};"
        : "+f"(c[0]), "+f"(c[1]), "+f"(c[2]), "+f"(c[3])
        : "r"(a[0]), "r"(a[1]), "r"(a[2]), "r"(a[3]),
          "r"(b[0]), "r"(b[1]));
}

// ---------------------------------------------------------------------------
// Kernel 1: QKV projection via tf32 tensor cores.
// C[m,n] = sum_k x[m,k] * W[n,k]   (NT), CTA tile 128x128x32, 8 warps (64x32).
// Writes [B,H,T,HD].  blockIdx.z selects Wq/Wk/Wv.
// ---------------------------------------------------------------------------
__global__ __launch_bounds__(256, 2) void qkv_tf32(
    const float* __restrict__ x,
    const float* __restrict__ Wq,
    const float* __restrict__ Wk,
    const float* __restrict__ Wv)
{
    __shared__ uint32_t As[128][36];   // row stride 36 -> conflict-free frag LDS
    __shared__ uint32_t Bs[128][36];

    const int tid  = threadIdx.x;
    const int lane = tid & 31;
    const int wid  = tid >> 5;
    const int lq   = lane >> 2;     // 0..7
    const int lr   = lane & 3;      // 0..3
    const int wm   = (wid & 1) * 64;
    const int wn   = (wid >> 1) * 32;
    const int m0   = blockIdx.x * 128;
    const int n0   = blockIdx.y * 128;
    const int z    = blockIdx.z;

    const float* __restrict__ W = (z == 0) ? Wq : (z == 1 ? Wk : Wv);
    float* __restrict__ outp    = (z == 0) ? g_Q : (z == 1 ? g_K : g_V);

    const int lrow = tid >> 3;        // 0..31
    const int lk   = (tid & 7) * 4;   // 0..28

    float acc[4][4][4];
#pragma unroll
    for (int i = 0; i < 4; i++)
#pragma unroll
        for (int j = 0; j < 4; j++)
#pragma unroll
            for (int v = 0; v < 4; v++) acc[i][j][v] = 0.0f;

    for (int k0 = 0; k0 < DIM_; k0 += 32) {
        uint32_t la[4][4], lb[4][4];
#pragma unroll
        for (int r = 0; r < 4; r++) {
            float4 va = *(const float4*)(x + (size_t)(m0 + lrow + 32 * r) * DIM_ + k0 + lk);
            la[r][0] = f2tf32(va.x); la[r][1] = f2tf32(va.y);
            la[r][2] = f2tf32(va.z); la[r][3] = f2tf32(va.w);
            float4 vb = *(const float4*)(W + (size_t)(n0 + lrow + 32 * r) * DIM_ + k0 + lk);
            lb[r][0] = f2tf32(vb.x); lb[r][1] = f2tf32(vb.y);
            lb[r][2] = f2tf32(vb.z); lb[r][3] = f2tf32(vb.w);
        }
        __syncthreads();
#pragma unroll
        for (int r = 0; r < 4; r++) {
            *(uint4*)&As[lrow + 32 * r][lk] = make_uint4(la[r][0], la[r][1], la[r][2], la[r][3]);
            *(uint4*)&Bs[lrow + 32 * r][lk] = make_uint4(lb[r][0], lb[r][1], lb[r][2], lb[r][3]);
        }
        __syncthreads();

#pragma unroll
        for (int ks = 0; ks < 32; ks += 8) {
            uint32_t a[4][4], b[4][2];
#pragma unroll
            for (int i = 0; i < 4; i++) {
                a[i][0] = As[wm + i * 16 + lq][ks + lr];
                a[i][1] = As[wm + i * 16 + 8 + lq][ks + lr];
                a[i][2] = As[wm + i * 16 + lq][ks + 4 + lr];
                a[i][3] = As[wm + i * 16 + 8 + lq][ks + 4 + lr];
            }
#pragma unroll
            for (int j = 0; j < 4; j++) {
                b[j][0] = Bs[wn + j * 8 + lq][ks + lr];
                b[j][1] = Bs[wn + j * 8 + lq][ks + 4 + lr];
            }
#pragma unroll
            for (int i = 0; i < 4; i++)
#pragma unroll
                for (int j = 0; j < 4; j++)
                    mma_tf32(acc[i][j], a[i], b[j]);
        }
        __syncthreads();
    }

    // Epilogue -> [B,H,T,HD]
#pragma unroll
    for (int i = 0; i < 4; i++) {
#pragma unroll
        for (int half = 0; half < 2; half++) {
            int row = m0 + wm + i * 16 + lq + 8 * half;
            int bb = row >> 11;
            int t  = row & (TLEN - 1);
#pragma unroll
            for (int j = 0; j < 4; j++) {
                int ncol = n0 + wn + j * 8 + 2 * lr;
                int head = ncol >> 6;
                int hd   = ncol & 63;
                float2 v = make_float2(acc[i][j][2 * half], acc[i][j][2 * half + 1]);
                *(float2*)(outp + (((size_t)(bb * NH + head)) * TLEN + t) * HDIM + hd) = v;
            }
        }
    }
}

// ---------------------------------------------------------------------------
// Kernel 2: RoPE on Q and K, in place.  Folds attention scale (1/8) into Q.
// ---------------------------------------------------------------------------
__global__ __launch_bounds__(256) void rope_kernel()
{
    int idx = blockIdx.x * 256 + threadIdx.x;    // BSZ*NH*TLEN*32 threads
    int j = idx & 31;
    int bht = idx >> 5;
    int t = bht & (TLEN - 1);
    float ang = (float)t * exp2f(-(float)j * (13.287712379549449f / 32.0f));
    float s, c;
    sincosf(ang, &s, &c);
    size_t base = (size_t)bht * HDIM;

    float q1 = g_Q[base + j], q2 = g_Q[base + j + 32];
    const float scale = 0.125f;   // HD^-0.5
    g_Q[base + j]      = (q1 * c - q2 * s) * scale;
    g_Q[base + j + 32] = (q2 * c + q1 * s) * scale;

    float k1 = g_K[base + j], k2 = g_K[base + j + 32];
    g_K[base + j]      = k1 * c - k2 * s;
    g_K[base + j + 32] = k2 * c + k1 * s;
}

// ---------------------------------------------------------------------------
// Kernel 3: flash attention (fp32, unchanged from R1 — converts next round).
// ---------------------------------------------------------------------------
__global__ __launch_bounds__(256) void attn_kernel(const int* __restrict__ mask)
{
    extern __shared__ float sm[];
    float* Qs = sm;                  // 64*64
    float* Ks = Qs + 64 * 64;        // 64*65
    float* Vs = Ks + 64 * 65;        // 64*64
    float* Ps = Vs + 64 * 64;        // 64*64

    const int tid = threadIdx.x;
    const int tx = tid & 15, ty = tid >> 4;
    const int qt = blockIdx.x;
    const int bh = blockIdx.y;
    const int bb = bh >> 4;

    const float* __restrict__ Qg = g_Q + ((size_t)bh * TLEN + qt * 64) * HDIM;
    const float* __restrict__ Kg = g_K + (size_t)bh * TLEN * HDIM;
    const float* __restrict__ Vg = g_V + (size_t)bh * TLEN * HDIM;
    const int* __restrict__ mrow = mask + (size_t)bb * TLEN;

    {
        int row = tid >> 4;
        int cq  = (tid & 15) * 4;
#pragma unroll
        for (int r = 0; r < 4; r++) {
            int rr = row + r * 16;
            *(float4*)&Qs[rr * 64 + cq] = *(const float4*)(Qg + (size_t)rr * 64 + cq);
        }
    }

    float m_i[4], l_i[4], o[4][4];
#pragma unroll
    for (int i = 0; i < 4; i++) {
        m_i[i] = -1e30f; l_i[i] = 0.0f;
#pragma unroll
        for (int j = 0; j < 4; j++) o[i][j] = 0.0f;
    }

    for (int kt = 0; kt < TLEN / 64; kt++) {
        __syncthreads();
        {
            int row = tid >> 4;
            int cq  = (tid & 15) * 4;
#pragma unroll
            for (int r = 0; r < 4; r++) {
                int rr = row + r * 16;
                float4 kv = *(const float4*)(Kg + ((size_t)kt * 64 + rr) * 64 + cq);
                Ks[rr * 65 + cq + 0] = kv.x; Ks[rr * 65 + cq + 1] = kv.y;
                Ks[rr * 65 + cq + 2] = kv.z; Ks[rr * 65 + cq + 3] = kv.w;
                *(float4*)&Vs[rr * 64 + cq] =
                    *(const float4*)(Vg + ((size_t)kt * 64 + rr) * 64 + cq);
            }
        }
        __syncthreads();

        float s4[4][4];
#pragma unroll
        for (int i = 0; i < 4; i++)
#pragma unroll
            for (int j = 0; j < 4; j++) s4[i][j] = 0.0f;

#pragma unroll 8
        for (int d = 0; d < 64; d++) {
            float a[4], b[4];
#pragma unroll
            for (int i = 0; i < 4; i++) a[i] = Qs[(ty * 4 + i) * 64 + d];
#pragma unroll
            for (int j = 0; j < 4; j++) b[j] = Ks[(tx * 4 + j) * 65 + d];
#pragma unroll
            for (int i = 0; i < 4; i++)
#pragma unroll
                for (int j = 0; j < 4; j++)
                    s4[i][j] += a[i] * b[j];
        }

        float madd[4];
#pragma unroll
        for (int j = 0; j < 4; j++)
            madd[j] = (1.0f - (float)mrow[kt * 64 + tx * 4 + j]) * 1e9f;
#pragma unroll
        for (int i = 0; i < 4; i++)
#pragma unroll
            for (int j = 0; j < 4; j++) s4[i][j] -= madd[j];

#pragma unroll
        for (int i = 0; i < 4; i++) {
            float rm = fmaxf(fmaxf(s4[i][0], s4[i][1]), fmaxf(s4[i][2], s4[i][3]));
#pragma unroll
            for (int off = 1; off < 16; off <<= 1)
                rm = fmaxf(rm, __shfl_xor_sync(0xffffffffu, rm, off));
            float mnew = fmaxf(m_i[i], rm);
            float corr = __expf(m_i[i] - mnew);
            float rsum = 0.0f;
#pragma unroll
            for (int j = 0; j < 4; j++) {
                s4[i][j] = __expf(s4[i][j] - mnew);
                rsum += s4[i][j];
            }
#pragma unroll
            for (int off = 1; off < 16; off <<= 1)
                rsum += __shfl_xor_sync(0xffffffffu, rsum, off);
            l_i[i] = l_i[i] * corr + rsum;
            m_i[i] = mnew;
#pragma unroll
            for (int j = 0; j < 4; j++) o[i][j] *= corr;
            *(float4*)&Ps[(ty * 4 + i) * 64 + tx * 4] =
                make_float4(s4[i][0], s4[i][1], s4[i][2], s4[i][3]);
        }
        __syncthreads();

#pragma unroll 8
        for (int k = 0; k < 64; k++) {
            float4 v = *(const float4*)&Vs[k * 64 + tx * 4];
#pragma unroll
            for (int i = 0; i < 4; i++) {
                float p = Ps[(ty * 4 + i) * 64 + k];
                o[i][0] += p * v.x; o[i][1] += p * v.y;
                o[i][2] += p * v.z; o[i][3] += p * v.w;
            }
        }
    }

#pragma unroll
    for (int i = 0; i < 4; i++) {
        float inv = 1.0f / l_i[i];
        float4 r = make_float4(o[i][0] * inv, o[i][1] * inv,
                               o[i][2] * inv, o[i][3] * inv);
        *(float4*)(g_O + ((size_t)bh * TLEN + qt * 64 + ty * 4 + i) * 64 + tx * 4) = r;
    }
}

// ---------------------------------------------------------------------------
// Kernel 4: output projection via tf32 mma + fused residual.
// A rows gathered from g_O [B,H,T,HD]; h = x + A@Wo^T -> g_Hh.
// ---------------------------------------------------------------------------
__global__ __launch_bounds__(256, 2) void oproj_tf32(
    const float* __restrict__ x,
    const float* __restrict__ Wo)
{
    __shared__ uint32_t As[128][36];
    __shared__ uint32_t Bs[128][36];

    const int tid  = threadIdx.x;
    const int lane = tid & 31;
    const int wid  = tid >> 5;
    const int lq   = lane >> 2;
    const int lr   = lane & 3;
    const int wm   = (wid & 1) * 64;
    const int wn   = (wid >> 1) * 32;
    const int m0   = blockIdx.x * 128;
    const int n0   = blockIdx.y * 128;

    const int lrow = tid >> 3;
    const int lk   = (tid & 7) * 4;

    float acc[4][4][4];
#pragma unroll
    for (int i = 0; i < 4; i++)
#pragma unroll
        for (int j = 0; j < 4; j++)
#pragma unroll
            for (int v = 0; v < 4; v++) acc[i][j][v] = 0.0f;

    for (int k0 = 0; k0 < DIM_; k0 += 32) {
        uint32_t la[4][4], lb[4][4];
#pragma unroll
        for (int r = 0; r < 4; r++) {
            int m  = m0 + lrow + 32 * r;
            int bb = m >> 11;
            int t  = m & (TLEN - 1);
            int kg = k0 + lk;
            int hh = kg >> 6;
            int hd = kg & 63;
            float4 va = *(const float4*)(g_O +
                (((size_t)(bb * NH + hh)) * TLEN + t) * HDIM + hd);
            la[r][0] = f2tf32(va.x); la[r][1] = f2tf32(va.y);
            la[r][2] = f2tf32(va.z); la[r][3] = f2tf32(va.w);
            float4 vb = *(const float4*)(Wo + (size_t)(n0 + lrow + 32 * r) * DIM_ + k0 + lk);
            lb[r][0] = f2tf32(vb.x); lb[r][1] = f2tf32(vb.y);
            lb[r][2] = f2tf32(vb.z); lb[r][3] = f2tf32(vb.w);
        }
        __syncthreads();
#pragma unroll
        for (int r = 0; r < 4; r++) {
            *(uint4*)&As[lrow + 32 * r][lk] = make_uint4(la[r][0], la[r][1], la[r][2], la[r][3]);
            *(uint4*)&Bs[lrow + 32 * r][lk] = make_uint4(lb[r][0], lb[r][1], lb[r][2], lb[r][3]);
        }
        __syncthreads();

#pragma unroll
        for (int ks = 0; ks < 32; ks += 8) {
            uint32_t a[4][4], b[4][2];
#pragma unroll
            for (int i = 0; i < 4; i++) {
                a[i][0] = As[wm + i * 16 + lq][ks + lr];
                a[i][1] = As[wm + i * 16 + 8 + lq][ks + lr];
                a[i][2] = As[wm + i * 16 + lq][ks + 4 + lr];
                a[i][3] = As[wm + i * 16 + 8 + lq][ks + 4 + lr];
            }
#pragma unroll
            for (int j = 0; j < 4; j++) {
                b[j][0] = Bs[wn + j * 8 + lq][ks + lr];
                b[j][1] = Bs[wn + j * 8 + lq][ks + 4 + lr];
            }
#pragma unroll
            for (int i = 0; i < 4; i++)
#pragma unroll
                for (int j = 0; j < 4; j++)
                    mma_tf32(acc[i][j], a[i], b[j]);
        }
        __syncthreads();
    }

    // Epilogue: h = x + proj -> g_Hh
#pragma unroll
    for (int i = 0; i < 4; i++) {
#pragma unroll
        for (int half = 0; half < 2; half++) {
            int row = m0 + wm + i * 16 + lq + 8 * half;
#pragma unroll
            for (int j = 0; j < 4; j++) {
                int ncol = n0 + wn + j * 8 + 2 * lr;
                size_t idx = (size_t)row * DIM_ + ncol;
                float2 xr = *(const float2*)(x + idx);
                float2 v = make_float2(acc[i][j][2 * half] + xr.x,
                                       acc[i][j][2 * half + 1] + xr.y);
                *(float2*)(g_Hh + idx) = v;
            }
        }
    }
}

// ---------------------------------------------------------------------------
// Kernel 5: LayerNorm per row of h. One CTA (256 threads) per row.
// ---------------------------------------------------------------------------
__global__ __launch_bounds__(256) void ln_kernel(
    const float* __restrict__ gamma,
    const float* __restrict__ beta,
    float* __restrict__ out)
{
    __shared__ float red0[8];
    __shared__ float red1[8];
    const int row = blockIdx.x;
    const int tid = threadIdx.x;
    const float* hr = g_Hh + (size_t)row * DIM_;

    float4 v = *(const float4*)(hr + tid * 4);
    float sum = v.x + v.y + v.z + v.w;
    float sq  = v.x * v.x + v.y * v.y + v.z * v.z + v.w * v.w;
#pragma unroll
    for (int off = 16; off; off >>= 1) {
        sum += __shfl_xor_sync(0xffffffffu, sum, off);
        sq  += __shfl_xor_sync(0xffffffffu, sq, off);
    }
    int wid = tid >> 5, lane = tid & 31;
    if (lane == 0) { red0[wid] = sum; red1[wid] = sq; }
    __syncthreads();

    float tot = 0.0f, totsq = 0.0f;
#pragma unroll
    for (int w = 0; w < 8; w++) { tot += red0[w]; totsq += red1[w]; }

    float mu = tot * (1.0f / DIM_);
    float var = totsq * (1.0f / DIM_) - mu * mu;
    float rs = rsqrtf(var + 1e-5f);

    int e = tid * 4;
    float4 g  = *(const float4*)(gamma + e);
    float4 be = *(const float4*)(beta + e);
    float4 r = make_float4((v.x - mu) * rs * g.x + be.x,
                           (v.y - mu) * rs * g.y + be.y,
                           (v.z - mu) * rs * g.z + be.z,
                           (v.w - mu) * rs * g.w + be.w);
    *(float4*)(out + (size_t)row * DIM_ + e) = r;
}

// ---------------------------------------------------------------------------
extern "C" void kernel_launch(void* const* d_in, const int* in_sizes, int n_in,
                              void* d_out, int out_size)
{
    const float* x     = (const float*)d_in[0];
    const int*   mask  = (const int*)d_in[1];
    const float* Wq    = (const float*)d_in[2];
    const float* Wk    = (const float*)d_in[3];
    const float* Wv    = (const float*)d_in[4];
    const float* Wo    = (const float*)d_in[5];
    const float* gamma = (const float*)d_in[6];
    const float* beta  = (const float*)d_in[7];
    float* out = (float*)d_out;

    const int attn_smem = (64 * 64 * 3 + 64 * 65) * 4;   // 65792 B
    cudaFuncSetAttribute(attn_kernel,
                         cudaFuncAttributeMaxDynamicSharedMemorySize, attn_smem);

    qkv_tf32<<<dim3(BT / 128, DIM_ / 128, 3), 256>>>(x, Wq, Wk, Wv);

    rope_kernel<<<(BSZ * NH * TLEN * 32) / 256, 256>>>();

    attn_kernel<<<dim3(TLEN / 64, BSZ * NH), 256, attn_smem>>>(mask);

    oproj_tf32<<<dim3(BT / 128, DIM_ / 128), 256>>>(x, Wo);

    ln_kernel<<<BT, 256>>>(gamma, beta, out);
}

// round 4
// speedup vs baseline: 3.1860x; 2.2306x over previous
#include <cuda_runtime.h>
#include <cuda_fp16.h>
#include <math.h>
#include <stddef.h>
#include <stdint.h>

#define BSZ   4
#define TLEN  2048
#define DIM_  1024
#define NH    16
#define HDIM  64
#define BT    (BSZ * TLEN)        // 8192

// Scratch (device-global; no runtime allocation)
__device__ float  g_Q[(size_t)BSZ * NH * TLEN * HDIM];
__device__ float  g_K[(size_t)BSZ * NH * TLEN * HDIM];
__device__ __half g_Vh[(size_t)BSZ * NH * HDIM * TLEN];   // [bh][d][t]
__device__ float  g_O[(size_t)BSZ * NH * TLEN * HDIM];
__device__ float  g_Hh[(size_t)BT * DIM_];

// ---------------------------------------------------------------------------
// mma helpers
// ---------------------------------------------------------------------------
__device__ __forceinline__ uint32_t f2tf32(float x) {
    uint32_t r;
    asm("cvt.rna.tf32.f32 %0, %1;" : "=r"(r) : "f"(x));
    return r;
}

__device__ __forceinline__ void mma_tf32(float c[4],
                                         const uint32_t a[4],
                                         const uint32_t b[2]) {
    asm volatile(
        "mma.sync.aligned.m16n8k8.row.col.f32.tf32.tf32.f32 "
        "{%0,%1,%2,%3},{%4,%5,%6,%7},{%8,%9},{%0,%1,%2,%3};"
        : "+f"(c[0]), "+f"(c[1]), "+f"(c[2]), "+f"(c[3])
        : "r"(a[0]), "r"(a[1]), "r"(a[2]), "r"(a[3]),
          "r"(b[0]), "r"(b[1]));
}

__device__ __forceinline__ void mma_f16(float c[4],
                                        const uint32_t a[4],
                                        uint32_t b0, uint32_t b1) {
    asm volatile(
        "mma.sync.aligned.m16n8k16.row.col.f32.f16.f16.f32 "
        "{%0,%1,%2,%3},{%4,%5,%6,%7},{%8,%9},{%0,%1,%2,%3};"
        : "+f"(c[0]), "+f"(c[1]), "+f"(c[2]), "+f"(c[3])
        : "r"(a[0]), "r"(a[1]), "r"(a[2]), "r"(a[3]),
          "r"(b0), "r"(b1));
}

__device__ __forceinline__ uint32_t pack_h2(float lo, float hi) {
    __half2 h = __floats2half2_rn(lo, hi);
    return *(uint32_t*)&h;
}

// ---------------------------------------------------------------------------
// Kernel 1: QKV projection via tf32 tensor cores.
// C[m,n] = sum_k x[m,k] * W[n,k]   (NT), CTA tile 128x128x32, 8 warps (64x32).
// Q,K -> fp32 [B,H,T,HD];  V -> half [bh][d][t].
// ---------------------------------------------------------------------------
__global__ __launch_bounds__(256, 2) void qkv_tf32(
    const float* __restrict__ x,
    const float* __restrict__ Wq,
    const float* __restrict__ Wk,
    const float* __restrict__ Wv)
{
    __shared__ uint32_t As[128][36];
    __shared__ uint32_t Bs[128][36];

    const int tid  = threadIdx.x;
    const int lane = tid & 31;
    const int wid  = tid >> 5;
    const int lq   = lane >> 2;
    const int lr   = lane & 3;
    const int wm   = (wid & 1) * 64;
    const int wn   = (wid >> 1) * 32;
    const int m0   = blockIdx.x * 128;
    const int n0   = blockIdx.y * 128;
    const int z    = blockIdx.z;

    const float* __restrict__ W = (z == 0) ? Wq : (z == 1 ? Wk : Wv);

    const int lrow = tid >> 3;
    const int lk   = (tid & 7) * 4;

    float acc[4][4][4];
#pragma unroll
    for (int i = 0; i < 4; i++)
#pragma unroll
        for (int j = 0; j < 4; j++)
#pragma unroll
            for (int v = 0; v < 4; v++) acc[i][j][v] = 0.0f;

    for (int k0 = 0; k0 < DIM_; k0 += 32) {
        uint32_t la[4][4], lb[4][4];
#pragma unroll
        for (int r = 0; r < 4; r++) {
            float4 va = *(const float4*)(x + (size_t)(m0 + lrow + 32 * r) * DIM_ + k0 + lk);
            la[r][0] = f2tf32(va.x); la[r][1] = f2tf32(va.y);
            la[r][2] = f2tf32(va.z); la[r][3] = f2tf32(va.w);
            float4 vb = *(const float4*)(W + (size_t)(n0 + lrow + 32 * r) * DIM_ + k0 + lk);
            lb[r][0] = f2tf32(vb.x); lb[r][1] = f2tf32(vb.y);
            lb[r][2] = f2tf32(vb.z); lb[r][3] = f2tf32(vb.w);
        }
        __syncthreads();
#pragma unroll
        for (int r = 0; r < 4; r++) {
            *(uint4*)&As[lrow + 32 * r][lk] = make_uint4(la[r][0], la[r][1], la[r][2], la[r][3]);
            *(uint4*)&Bs[lrow + 32 * r][lk] = make_uint4(lb[r][0], lb[r][1], lb[r][2], lb[r][3]);
        }
        __syncthreads();

#pragma unroll
        for (int ks = 0; ks < 32; ks += 8) {
            uint32_t a[4][4], b[4][2];
#pragma unroll
            for (int i = 0; i < 4; i++) {
                a[i][0] = As[wm + i * 16 + lq][ks + lr];
                a[i][1] = As[wm + i * 16 + 8 + lq][ks + lr];
                a[i][2] = As[wm + i * 16 + lq][ks + 4 + lr];
                a[i][3] = As[wm + i * 16 + 8 + lq][ks + 4 + lr];
            }
#pragma unroll
            for (int j = 0; j < 4; j++) {
                b[j][0] = Bs[wn + j * 8 + lq][ks + lr];
                b[j][1] = Bs[wn + j * 8 + lq][ks + 4 + lr];
            }
#pragma unroll
            for (int i = 0; i < 4; i++)
#pragma unroll
                for (int j = 0; j < 4; j++)
                    mma_tf32(acc[i][j], a[i], b[j]);
        }
        __syncthreads();
    }

    // Epilogue
#pragma unroll
    for (int i = 0; i < 4; i++) {
#pragma unroll
        for (int half_ = 0; half_ < 2; half_++) {
            int row = m0 + wm + i * 16 + lq + 8 * half_;
            int bb = row >> 11;
            int t  = row & (TLEN - 1);
#pragma unroll
            for (int j = 0; j < 4; j++) {
                int ncol = n0 + wn + j * 8 + 2 * lr;
                int head = ncol >> 6;
                int hd   = ncol & 63;
                float v0 = acc[i][j][2 * half_];
                float v1 = acc[i][j][2 * half_ + 1];
                if (z == 2) {
                    size_t base = ((size_t)(bb * NH + head) * HDIM + hd) * TLEN + t;
                    g_Vh[base]        = __float2half(v0);
                    g_Vh[base + TLEN] = __float2half(v1);
                } else {
                    float* outp = (z == 0) ? g_Q : g_K;
                    *(float2*)(outp + (((size_t)(bb * NH + head)) * TLEN + t) * HDIM + hd) =
                        make_float2(v0, v1);
                }
            }
        }
    }
}

// ---------------------------------------------------------------------------
// Kernel 2: RoPE on Q and K, in place.  Folds attention scale (1/8) into Q.
// ---------------------------------------------------------------------------
__global__ __launch_bounds__(256) void rope_kernel()
{
    int idx = blockIdx.x * 256 + threadIdx.x;
    int j = idx & 31;
    int bht = idx >> 5;
    int t = bht & (TLEN - 1);
    float ang = (float)t * exp2f(-(float)j * (13.287712379549449f / 32.0f));
    float s, c;
    sincosf(ang, &s, &c);
    size_t base = (size_t)bht * HDIM;

    float q1 = g_Q[base + j], q2 = g_Q[base + j + 32];
    const float scale = 0.125f;
    g_Q[base + j]      = (q1 * c - q2 * s) * scale;
    g_Q[base + j + 32] = (q2 * c + q1 * s) * scale;

    float k1 = g_K[base + j], k2 = g_K[base + j + 32];
    g_K[base + j]      = k1 * c - k2 * s;
    g_K[base + j + 32] = k2 * c + k1 * s;
}

// ---------------------------------------------------------------------------
// Kernel 3: flash attention on tensor cores.
// CTA = 128 q-rows x one (b,h); 8 warps, each owns 16 q-rows x all 128 keys.
// S via tf32 m16n8k8; P stays in registers (C-frag == A-frag of m16n8k16 f16);
// PV via fp16 m16n8k16 with V(half) B-frags from conflict-free smem.
// ---------------------------------------------------------------------------
#define KS_STRIDE 68          // words per K row (conflict-free frags)
#define VH_STRIDE 136         // halves per V row (bank = 4*lq+lr, distinct)
#define ATTN_SMEM (128 * KS_STRIDE * 4 + 64 * VH_STRIDE * 2 + 128 * 4)

__global__ __launch_bounds__(256) void attn_mma(const int* __restrict__ mask)
{
    extern __shared__ char smraw[];
    uint32_t* Ks   = (uint32_t*)smraw;                               // 128 x 68 words
    __half*   Vh   = (__half*)(smraw + 128 * KS_STRIDE * 4);          // 64 x 136 halves
    float*    madds = (float*)(smraw + 128 * KS_STRIDE * 4 + 64 * VH_STRIDE * 2);

    const int tid  = threadIdx.x;
    const int lane = tid & 31;
    const int wid  = tid >> 5;
    const int lq   = lane >> 2;
    const int lr   = lane & 3;
    const int qt   = blockIdx.x;
    const int bh   = blockIdx.y;
    const int bb   = bh >> 4;
    const int q0   = qt * 128 + wid * 16;

    const float*  __restrict__ Qg = g_Q + ((size_t)bh * TLEN + q0) * HDIM;
    const float*  __restrict__ Kg = g_K + (size_t)bh * TLEN * HDIM;
    const __half* __restrict__ Vg = g_Vh + (size_t)bh * HDIM * TLEN;
    const int*    __restrict__ mrow = mask + (size_t)bb * TLEN;

    // Q fragments (scale already folded in by rope): resident all kernel.
    uint32_t aq[8][4];
#pragma unroll
    for (int ks = 0; ks < 8; ks++) {
        aq[ks][0] = f2tf32(Qg[lq * 64 + ks * 8 + lr]);
        aq[ks][1] = f2tf32(Qg[(lq + 8) * 64 + ks * 8 + lr]);
        aq[ks][2] = f2tf32(Qg[lq * 64 + ks * 8 + 4 + lr]);
        aq[ks][3] = f2tf32(Qg[(lq + 8) * 64 + ks * 8 + 4 + lr]);
    }

    float oacc[8][4];
#pragma unroll
    for (int dn = 0; dn < 8; dn++)
#pragma unroll
        for (int v = 0; v < 4; v++) oacc[dn][v] = 0.0f;
    float mA = -1e30f, mB = -1e30f, lA = 0.0f, lB = 0.0f;

    for (int kt = 0; kt < 16; kt++) {
        __syncthreads();
        // --- fill K tile (tf32, column pairs (d, d+4) interleaved) ---
#pragma unroll
        for (int i = 0; i < 8; i++) {
            int linear = tid + i * 256;            // 0..2047
            int row  = linear >> 4;
            int colq = (linear & 15) * 4;
            float4 v = *(const float4*)(Kg + ((size_t)kt * 128 + row) * 64 + colq);
            int grp   = (colq >> 3) * 8;
            int half_ = (colq >> 2) & 1;
            uint32_t* dst = &Ks[row * KS_STRIDE + grp + half_];
            dst[0] = f2tf32(v.x); dst[2] = f2tf32(v.y);
            dst[4] = f2tf32(v.z); dst[6] = f2tf32(v.w);
        }
        // --- fill V tile (half, [d][key]) ---
#pragma unroll
        for (int i = 0; i < 4; i++) {
            int linear = tid + i * 256;            // 0..1023
            int d  = linear >> 4;
            int kp = (linear & 15) * 8;
            uint4 v = *(const uint4*)(Vg + (size_t)d * TLEN + kt * 128 + kp);
            *(uint4*)&Vh[d * VH_STRIDE + kp] = v;
        }
        if (tid < 128)
            madds[tid] = (1.0f - (float)mrow[kt * 128 + tid]) * 1e9f;
        __syncthreads();

        // --- S = Q K^T (16 n-tiles of 8 keys, 8 k-steps) ---
        float sacc[16][4];
#pragma unroll
        for (int j = 0; j < 16; j++)
#pragma unroll
            for (int v = 0; v < 4; v++) sacc[j][v] = 0.0f;

#pragma unroll
        for (int j = 0; j < 16; j++) {
#pragma unroll
            for (int ks = 0; ks < 8; ks++) {
                uint32_t b[2];
                *(uint2*)b = *(const uint2*)&Ks[(j * 8 + lq) * KS_STRIDE + ks * 8 + 2 * lr];
                mma_tf32(sacc[j], aq[ks], b);
            }
        }

        // --- mask + online softmax (rows lq and lq+8; 4-lane row groups) ---
        float rmaxA = -1e30f, rmaxB = -1e30f;
#pragma unroll
        for (int j = 0; j < 16; j++) {
            float m0v = madds[j * 8 + 2 * lr];
            float m1v = madds[j * 8 + 2 * lr + 1];
            sacc[j][0] -= m0v; sacc[j][1] -= m1v;
            sacc[j][2] -= m0v; sacc[j][3] -= m1v;
            rmaxA = fmaxf(rmaxA, fmaxf(sacc[j][0], sacc[j][1]));
            rmaxB = fmaxf(rmaxB, fmaxf(sacc[j][2], sacc[j][3]));
        }
        rmaxA = fmaxf(rmaxA, __shfl_xor_sync(0xffffffffu, rmaxA, 1));
        rmaxA = fmaxf(rmaxA, __shfl_xor_sync(0xffffffffu, rmaxA, 2));
        rmaxB = fmaxf(rmaxB, __shfl_xor_sync(0xffffffffu, rmaxB, 1));
        rmaxB = fmaxf(rmaxB, __shfl_xor_sync(0xffffffffu, rmaxB, 2));

        float mnA = fmaxf(mA, rmaxA), mnB = fmaxf(mB, rmaxB);
        float cA = __expf(mA - mnA),  cB = __expf(mB - mnB);
        float sumA = 0.0f, sumB = 0.0f;

        uint32_t pa[8][4];
#pragma unroll
        for (int s = 0; s < 8; s++) {
            float p0 = __expf(sacc[2 * s][0] - mnA);
            float p1 = __expf(sacc[2 * s][1] - mnA);
            float p2 = __expf(sacc[2 * s][2] - mnB);
            float p3 = __expf(sacc[2 * s][3] - mnB);
            float p4 = __expf(sacc[2 * s + 1][0] - mnA);
            float p5 = __expf(sacc[2 * s + 1][1] - mnA);
            float p6 = __expf(sacc[2 * s + 1][2] - mnB);
            float p7 = __expf(sacc[2 * s + 1][3] - mnB);
            sumA += p0 + p1 + p4 + p5;
            sumB += p2 + p3 + p6 + p7;
            pa[s][0] = pack_h2(p0, p1);
            pa[s][1] = pack_h2(p2, p3);
            pa[s][2] = pack_h2(p4, p5);
            pa[s][3] = pack_h2(p6, p7);
        }
        sumA += __shfl_xor_sync(0xffffffffu, sumA, 1);
        sumA += __shfl_xor_sync(0xffffffffu, sumA, 2);
        sumB += __shfl_xor_sync(0xffffffffu, sumB, 1);
        sumB += __shfl_xor_sync(0xffffffffu, sumB, 2);

        lA = lA * cA + sumA;  lB = lB * cB + sumB;
        mA = mnA;             mB = mnB;
#pragma unroll
        for (int dn = 0; dn < 8; dn++) {
            oacc[dn][0] *= cA; oacc[dn][1] *= cA;
            oacc[dn][2] *= cB; oacc[dn][3] *= cB;
        }

        // --- O += P @ V  (8 k-blocks of 16 keys, 8 d-tiles of 8 cols) ---
#pragma unroll
        for (int s = 0; s < 8; s++) {
#pragma unroll
            for (int dn = 0; dn < 8; dn++) {
                const __half* vb = &Vh[(dn * 8 + lq) * VH_STRIDE + s * 16 + 2 * lr];
                uint32_t b0 = *(const uint32_t*)vb;
                uint32_t b1 = *(const uint32_t*)(vb + 8);
                mma_f16(oacc[dn], pa[s], b0, b1);
            }
        }
    }

    // --- normalize + write [bh][t][d] ---
    float invA = 1.0f / lA, invB = 1.0f / lB;
#pragma unroll
    for (int dn = 0; dn < 8; dn++) {
        *(float2*)(g_O + ((size_t)bh * TLEN + q0 + lq) * HDIM + dn * 8 + 2 * lr) =
            make_float2(oacc[dn][0] * invA, oacc[dn][1] * invA);
        *(float2*)(g_O + ((size_t)bh * TLEN + q0 + lq + 8) * HDIM + dn * 8 + 2 * lr) =
            make_float2(oacc[dn][2] * invB, oacc[dn][3] * invB);
    }
}

// ---------------------------------------------------------------------------
// Kernel 4: output projection via tf32 mma + fused residual.
// ---------------------------------------------------------------------------
__global__ __launch_bounds__(256, 2) void oproj_tf32(
    const float* __restrict__ x,
    const float* __restrict__ Wo)
{
    __shared__ uint32_t As[128][36];
    __shared__ uint32_t Bs[128][36];

    const int tid  = threadIdx.x;
    const int lane = tid & 31;
    const int wid  = tid >> 5;
    const int lq   = lane >> 2;
    const int lr   = lane & 3;
    const int wm   = (wid & 1) * 64;
    const int wn   = (wid >> 1) * 32;
    const int m0   = blockIdx.x * 128;
    const int n0   = blockIdx.y * 128;

    const int lrow = tid >> 3;
    const int lk   = (tid & 7) * 4;

    float acc[4][4][4];
#pragma unroll
    for (int i = 0; i < 4; i++)
#pragma unroll
        for (int j = 0; j < 4; j++)
#pragma unroll
            for (int v = 0; v < 4; v++) acc[i][j][v] = 0.0f;

    for (int k0 = 0; k0 < DIM_; k0 += 32) {
        uint32_t la[4][4], lb[4][4];
#pragma unroll
        for (int r = 0; r < 4; r++) {
            int m  = m0 + lrow + 32 * r;
            int bb = m >> 11;
            int t  = m & (TLEN - 1);
            int kg = k0 + lk;
            int hh = kg >> 6;
            int hd = kg & 63;
            float4 va = *(const float4*)(g_O +
                (((size_t)(bb * NH + hh)) * TLEN + t) * HDIM + hd);
            la[r][0] = f2tf32(va.x); la[r][1] = f2tf32(va.y);
            la[r][2] = f2tf32(va.z); la[r][3] = f2tf32(va.w);
            float4 vb = *(const float4*)(Wo + (size_t)(n0 + lrow + 32 * r) * DIM_ + k0 + lk);
            lb[r][0] = f2tf32(vb.x); lb[r][1] = f2tf32(vb.y);
            lb[r][2] = f2tf32(vb.z); lb[r][3] = f2tf32(vb.w);
        }
        __syncthreads();
#pragma unroll
        for (int r = 0; r < 4; r++) {
            *(uint4*)&As[lrow + 32 * r][lk] = make_uint4(la[r][0], la[r][1], la[r][2], la[r][3]);
            *(uint4*)&Bs[lrow + 32 * r][lk] = make_uint4(lb[r][0], lb[r][1], lb[r][2], lb[r][3]);
        }
        __syncthreads();

#pragma unroll
        for (int ks = 0; ks < 32; ks += 8) {
            uint32_t a[4][4], b[4][2];
#pragma unroll
            for (int i = 0; i < 4; i++) {
                a[i][0] = As[wm + i * 16 + lq][ks + lr];
                a[i][1] = As[wm + i * 16 + 8 + lq][ks + lr];
                a[i][2] = As[wm + i * 16 + lq][ks + 4 + lr];
                a[i][3] = As[wm + i * 16 + 8 + lq][ks + 4 + lr];
            }
#pragma unroll
            for (int j = 0; j < 4; j++) {
                b[j][0] = Bs[wn + j * 8 + lq][ks + lr];
                b[j][1] = Bs[wn + j * 8 + lq][ks + 4 + lr];
            }
#pragma unroll
            for (int i = 0; i < 4; i++)
#pragma unroll
                for (int j = 0; j < 4; j++)
                    mma_tf32(acc[i][j], a[i], b[j]);
        }
        __syncthreads();
    }

#pragma unroll
    for (int i = 0; i < 4; i++) {
#pragma unroll
        for (int half_ = 0; half_ < 2; half_++) {
            int row = m0 + wm + i * 16 + lq + 8 * half_;
#pragma unroll
            for (int j = 0; j < 4; j++) {
                int ncol = n0 + wn + j * 8 + 2 * lr;
                size_t idx = (size_t)row * DIM_ + ncol;
                float2 xr = *(const float2*)(x + idx);
                float2 v = make_float2(acc[i][j][2 * half_] + xr.x,
                                       acc[i][j][2 * half_ + 1] + xr.y);
                *(float2*)(g_Hh + idx) = v;
            }
        }
    }
}

// ---------------------------------------------------------------------------
// Kernel 5: LayerNorm per row of h.
// ---------------------------------------------------------------------------
__global__ __launch_bounds__(256) void ln_kernel(
    const float* __restrict__ gamma,
    const float* __restrict__ beta,
    float* __restrict__ out)
{
    __shared__ float red0[8];
    __shared__ float red1[8];
    const int row = blockIdx.x;
    const int tid = threadIdx.x;
    const float* hr = g_Hh + (size_t)row * DIM_;

    float4 v = *(const float4*)(hr + tid * 4);
    float sum = v.x + v.y + v.z + v.w;
    float sq  = v.x * v.x + v.y * v.y + v.z * v.z + v.w * v.w;
#pragma unroll
    for (int off = 16; off; off >>= 1) {
        sum += __shfl_xor_sync(0xffffffffu, sum, off);
        sq  += __shfl_xor_sync(0xffffffffu, sq, off);
    }
    int wid = tid >> 5, lane = tid & 31;
    if (lane == 0) { red0[wid] = sum; red1[wid] = sq; }
    __syncthreads();

    float tot = 0.0f, totsq = 0.0f;
#pragma unroll
    for (int w = 0; w < 8; w++) { tot += red0[w]; totsq += red1[w]; }

    float mu = tot * (1.0f / DIM_);
    float var = totsq * (1.0f / DIM_) - mu * mu;
    float rs = rsqrtf(var + 1e-5f);

    int e = tid * 4;
    float4 g  = *(const float4*)(gamma + e);
    float4 be = *(const float4*)(beta + e);
    float4 r = make_float4((v.x - mu) * rs * g.x + be.x,
                           (v.y - mu) * rs * g.y + be.y,
                           (v.z - mu) * rs * g.z + be.z,
                           (v.w - mu) * rs * g.w + be.w);
    *(float4*)(out + (size_t)row * DIM_ + e) = r;
}

// ---------------------------------------------------------------------------
extern "C" void kernel_launch(void* const* d_in, const int* in_sizes, int n_in,
                              void* d_out, int out_size)
{
    const float* x     = (const float*)d_in[0];
    const int*   mask  = (const int*)d_in[1];
    const float* Wq    = (const float*)d_in[2];
    const float* Wk    = (const float*)d_in[3];
    const float* Wv    = (const float*)d_in[4];
    const float* Wo    = (const float*)d_in[5];
    const float* gamma = (const float*)d_in[6];
    const float* beta  = (const float*)d_in[7];
    float* out = (float*)d_out;

    cudaFuncSetAttribute(attn_mma,
                         cudaFuncAttributeMaxDynamicSharedMemorySize, ATTN_SMEM);

    qkv_tf32<<<dim3(BT / 128, DIM_ / 128, 3), 256>>>(x, Wq, Wk, Wv);

    rope_kernel<<<(BSZ * NH * TLEN * 32) / 256, 256>>>();

    attn_mma<<<dim3(TLEN / 128, BSZ * NH), 256, ATTN_SMEM>>>(mask);

    oproj_tf32<<<dim3(BT / 128, DIM_ / 128), 256>>>(x, Wo);

    ln_kernel<<<BT, 256>>>(gamma, beta, out);
}

// round 5
// speedup vs baseline: 4.9517x; 1.5542x over previous
#include <cuda_runtime.h>
#include <cuda_fp16.h>
#include <math.h>
#include <stddef.h>
#include <stdint.h>

#define BSZ   4
#define TLEN  2048
#define DIM_  1024
#define NH    16
#define HDIM  64
#define BT    (BSZ * TLEN)        // 8192

// Scratch (device-global; no runtime allocation)
__device__ __half g_Qh[(size_t)BSZ * NH * TLEN * HDIM];   // [bh][t][d], rope+scale applied
__device__ __half g_Kh[(size_t)BSZ * NH * TLEN * HDIM];   // [bh][t][d], rope applied
__device__ __half g_Vh[(size_t)BSZ * NH * HDIM * TLEN];   // [bh][d][t]
__device__ __half g_Oh[(size_t)BT * DIM_];                // [bt][dim] attention out
__device__ float  g_Hh[(size_t)BT * DIM_];                // residual sum

// ---------------------------------------------------------------------------
// mma helper: m16n8k16 fp16 inputs, fp32 accumulate
// ---------------------------------------------------------------------------
__device__ __forceinline__ void mma_f16(float c[4],
                                        const uint32_t a[4],
                                        uint32_t b0, uint32_t b1) {
    asm volatile(
        "mma.sync.aligned.m16n8k16.row.col.f32.f16.f16.f32 "
        "{%0,%1,%2,%3},{%4,%5,%6,%7},{%8,%9},{%0,%1,%2,%3};"
        : "+f"(c[0]), "+f"(c[1]), "+f"(c[2]), "+f"(c[3])
        : "r"(a[0]), "r"(a[1]), "r"(a[2]), "r"(a[3]),
          "r"(b0), "r"(b1));
}

__device__ __forceinline__ uint32_t pack_h2(float lo, float hi) {
    __half2 h = __floats2half2_rn(lo, hi);
    return *(uint32_t*)&h;
}

#define SMS 72   // smem row stride in halves (36 words -> conflict-free frags)

// ---------------------------------------------------------------------------
// Kernel 1: QKV projection, fp16 mma, RoPE fused in epilogue.
// C[m,n] = sum_k x[m,k] * W[n,k]  (NT).  CTA 128x128x32, 8 warps of 32x64.
// z=0 -> Q (rope+scale, half [bh][t][d]); z=1 -> K (rope, half);
// z=2 -> V (half [bh][d][t]).
// ---------------------------------------------------------------------------
__global__ __launch_bounds__(256, 2) void qkv_f16(
    const float* __restrict__ x,
    const float* __restrict__ Wq,
    const float* __restrict__ Wk,
    const float* __restrict__ Wv)
{
    __shared__ __half As[128][SMS];
    __shared__ __half Bs[128][SMS];

    const int tid  = threadIdx.x;
    const int lane = tid & 31;
    const int wid  = tid >> 5;
    const int lq   = lane >> 2;
    const int lr   = lane & 3;
    const int wm   = (wid & 3) * 32;      // 4 m-tiles of 32
    const int wn   = (wid >> 2) * 64;     // 2 n-tiles of 64 (full head)
    const int m0   = blockIdx.x * 128;
    const int n0   = blockIdx.y * 128;
    const int z    = blockIdx.z;

    const float* __restrict__ W = (z == 0) ? Wq : (z == 1 ? Wk : Wv);

    const int lrow = tid >> 3;            // 0..31
    const int lk   = (tid & 7) * 4;       // 0..28

    float acc[2][8][4];
#pragma unroll
    for (int i = 0; i < 2; i++)
#pragma unroll
        for (int j = 0; j < 8; j++)
#pragma unroll
            for (int v = 0; v < 4; v++) acc[i][j][v] = 0.0f;

    for (int k0 = 0; k0 < DIM_; k0 += 32) {
        uint32_t la[4][2], lb[4][2];
#pragma unroll
        for (int r = 0; r < 4; r++) {
            float4 va = *(const float4*)(x + (size_t)(m0 + lrow + 32 * r) * DIM_ + k0 + lk);
            la[r][0] = pack_h2(va.x, va.y);
            la[r][1] = pack_h2(va.z, va.w);
            float4 vb = *(const float4*)(W + (size_t)(n0 + lrow + 32 * r) * DIM_ + k0 + lk);
            lb[r][0] = pack_h2(vb.x, vb.y);
            lb[r][1] = pack_h2(vb.z, vb.w);
        }
        __syncthreads();
#pragma unroll
        for (int r = 0; r < 4; r++) {
            *(uint2*)&As[lrow + 32 * r][lk] = make_uint2(la[r][0], la[r][1]);
            *(uint2*)&Bs[lrow + 32 * r][lk] = make_uint2(lb[r][0], lb[r][1]);
        }
        __syncthreads();

#pragma unroll
        for (int ks = 0; ks < 32; ks += 16) {
            uint32_t a[2][4];
#pragma unroll
            for (int i = 0; i < 2; i++) {
                a[i][0] = *(const uint32_t*)&As[wm + i * 16 + lq][ks + 2 * lr];
                a[i][1] = *(const uint32_t*)&As[wm + i * 16 + 8 + lq][ks + 2 * lr];
                a[i][2] = *(const uint32_t*)&As[wm + i * 16 + lq][ks + 2 * lr + 8];
                a[i][3] = *(const uint32_t*)&As[wm + i * 16 + 8 + lq][ks + 2 * lr + 8];
            }
#pragma unroll
            for (int j = 0; j < 8; j++) {
                uint32_t b0 = *(const uint32_t*)&Bs[wn + j * 8 + lq][ks + 2 * lr];
                uint32_t b1 = *(const uint32_t*)&Bs[wn + j * 8 + lq][ks + 2 * lr + 8];
#pragma unroll
                for (int i = 0; i < 2; i++)
                    mma_f16(acc[i][j], a[i], b0, b1);
            }
        }
        __syncthreads();
    }

    // ---- Epilogue ----
    if (z < 2) {
        // RoPE fused: pair (hd, hd+32) == (j, j+4) within this thread.
        const float C32 = 13.287712379549449f / 32.0f;  // log2(10000)/32
        float fr[4][2];
#pragma unroll
        for (int jl = 0; jl < 4; jl++) {
            fr[jl][0] = exp2f(-(float)(jl * 8 + 2 * lr) * C32);
            fr[jl][1] = exp2f(-(float)(jl * 8 + 2 * lr + 1) * C32);
        }
        const float qs = (z == 0) ? 0.125f : 1.0f;
        __half* __restrict__ outp = (z == 0) ? g_Qh : g_Kh;

#pragma unroll
        for (int i = 0; i < 2; i++) {
#pragma unroll
            for (int half_ = 0; half_ < 2; half_++) {
                int row = m0 + wm + i * 16 + lq + 8 * half_;
                int bb = row >> 11;
                int t  = row & (TLEN - 1);
                float tf = (float)t;
#pragma unroll
                for (int jl = 0; jl < 4; jl++) {
                    int ncol = n0 + wn + jl * 8 + 2 * lr;
                    int head = ncol >> 6;
                    int hd1  = ncol & 63;     // < 32
                    float o1[2], o2[2];
#pragma unroll
                    for (int v = 0; v < 2; v++) {
                        float s, c;
                        sincosf(tf * fr[jl][v], &s, &c);
                        float q1 = acc[i][jl][2 * half_ + v];
                        float q2 = acc[i][jl + 4][2 * half_ + v];
                        o1[v] = (q1 * c - q2 * s) * qs;
                        o2[v] = (q2 * c + q1 * s) * qs;
                    }
                    size_t base = (((size_t)(bb * NH + head)) * TLEN + t) * HDIM;
                    *(__half2*)&outp[base + hd1] = __floats2half2_rn(o1[0], o1[1]);
                    *(__half2*)&outp[base + hd1 + 32] = __floats2half2_rn(o2[0], o2[1]);
                }
            }
        }
    } else {
        // V -> [bh][d][t]
#pragma unroll
        for (int i = 0; i < 2; i++) {
#pragma unroll
            for (int half_ = 0; half_ < 2; half_++) {
                int row = m0 + wm + i * 16 + lq + 8 * half_;
                int bb = row >> 11;
                int t  = row & (TLEN - 1);
#pragma unroll
                for (int j = 0; j < 8; j++) {
                    int ncol = n0 + wn + j * 8 + 2 * lr;
                    int head = ncol >> 6;
                    int hd   = ncol & 63;
                    size_t base = ((size_t)(bb * NH + head) * HDIM + hd) * TLEN + t;
                    g_Vh[base]        = __float2half(acc[i][j][2 * half_]);
                    g_Vh[base + TLEN] = __float2half(acc[i][j][2 * half_ + 1]);
                }
            }
        }
    }
}

// ---------------------------------------------------------------------------
// Kernel 2: flash attention, all-fp16 mma.
// CTA = 128 q-rows x one (b,h); 8 warps, each 16 q-rows x all 128 keys.
// ---------------------------------------------------------------------------
#define VH_STRIDE 136         // halves per V row
#define ATTN_SMEM (128 * SMS * 2 + 64 * VH_STRIDE * 2 + 128 * 4)

__global__ __launch_bounds__(256) void attn_mma(const int* __restrict__ mask)
{
    extern __shared__ char smraw[];
    __half* Ksm  = (__half*)smraw;                                   // 128 x 72 halves
    __half* Vh   = (__half*)(smraw + 128 * SMS * 2);                  // 64 x 136 halves
    float*  madds = (float*)(smraw + 128 * SMS * 2 + 64 * VH_STRIDE * 2);

    const int tid  = threadIdx.x;
    const int lane = tid & 31;
    const int wid  = tid >> 5;
    const int lq   = lane >> 2;
    const int lr   = lane & 3;
    const int qt   = blockIdx.x;
    const int bh   = blockIdx.y;
    const int bb   = bh >> 4;
    const int q0   = qt * 128 + wid * 16;

    const __half* __restrict__ Qg = g_Qh + ((size_t)bh * TLEN + q0) * HDIM;
    const __half* __restrict__ Kg = g_Kh + (size_t)bh * TLEN * HDIM;
    const __half* __restrict__ Vg = g_Vh + (size_t)bh * HDIM * TLEN;
    const int*    __restrict__ mrow = mask + (size_t)bb * TLEN;

    // Q fragments, resident (scale folded): 4 k-steps of 16.
    uint32_t aq[4][4];
#pragma unroll
    for (int ks = 0; ks < 4; ks++) {
        aq[ks][0] = *(const uint32_t*)&Qg[lq * 64 + ks * 16 + 2 * lr];
        aq[ks][1] = *(const uint32_t*)&Qg[(lq + 8) * 64 + ks * 16 + 2 * lr];
        aq[ks][2] = *(const uint32_t*)&Qg[lq * 64 + ks * 16 + 2 * lr + 8];
        aq[ks][3] = *(const uint32_t*)&Qg[(lq + 8) * 64 + ks * 16 + 2 * lr + 8];
    }

    float oacc[8][4];
#pragma unroll
    for (int dn = 0; dn < 8; dn++)
#pragma unroll
        for (int v = 0; v < 4; v++) oacc[dn][v] = 0.0f;
    float mA = -1e30f, mB = -1e30f, lA = 0.0f, lB = 0.0f;

    for (int kt = 0; kt < 16; kt++) {
        __syncthreads();
        // K tile: 128 rows x 64 halves, smem stride 72
#pragma unroll
        for (int i = 0; i < 4; i++) {
            int chunk = tid + i * 256;          // 0..1023
            int row = chunk >> 3;
            int c8  = (chunk & 7) * 8;
            uint4 v = *(const uint4*)(Kg + ((size_t)kt * 128 + row) * 64 + c8);
            *(uint4*)&Ksm[row * SMS + c8] = v;
        }
        // V tile: 64 rows (d) x 128 halves (keys), stride 136
#pragma unroll
        for (int i = 0; i < 4; i++) {
            int linear = tid + i * 256;         // 0..1023
            int d  = linear >> 4;
            int kp = (linear & 15) * 8;
            uint4 v = *(const uint4*)(Vg + (size_t)d * TLEN + kt * 128 + kp);
            *(uint4*)&Vh[d * VH_STRIDE + kp] = v;
        }
        if (tid < 128)
            madds[tid] = (1.0f - (float)mrow[kt * 128 + tid]) * 1e9f;
        __syncthreads();

        // S = Q K^T : 16 n-tiles x 4 k-steps
        float sacc[16][4];
#pragma unroll
        for (int j = 0; j < 16; j++)
#pragma unroll
            for (int v = 0; v < 4; v++) sacc[j][v] = 0.0f;

#pragma unroll
        for (int j = 0; j < 16; j++) {
#pragma unroll
            for (int ks = 0; ks < 4; ks++) {
                uint32_t b0 = *(const uint32_t*)&Ksm[(j * 8 + lq) * SMS + ks * 16 + 2 * lr];
                uint32_t b1 = *(const uint32_t*)&Ksm[(j * 8 + lq) * SMS + ks * 16 + 2 * lr + 8];
                mma_f16(sacc[j], aq[ks], b0, b1);
            }
        }

        // mask + online softmax
        float rmaxA = -1e30f, rmaxB = -1e30f;
#pragma unroll
        for (int j = 0; j < 16; j++) {
            float m0v = madds[j * 8 + 2 * lr];
            float m1v = madds[j * 8 + 2 * lr + 1];
            sacc[j][0] -= m0v; sacc[j][1] -= m1v;
            sacc[j][2] -= m0v; sacc[j][3] -= m1v;
            rmaxA = fmaxf(rmaxA, fmaxf(sacc[j][0], sacc[j][1]));
            rmaxB = fmaxf(rmaxB, fmaxf(sacc[j][2], sacc[j][3]));
        }
        rmaxA = fmaxf(rmaxA, __shfl_xor_sync(0xffffffffu, rmaxA, 1));
        rmaxA = fmaxf(rmaxA, __shfl_xor_sync(0xffffffffu, rmaxA, 2));
        rmaxB = fmaxf(rmaxB, __shfl_xor_sync(0xffffffffu, rmaxB, 1));
        rmaxB = fmaxf(rmaxB, __shfl_xor_sync(0xffffffffu, rmaxB, 2));

        float mnA = fmaxf(mA, rmaxA), mnB = fmaxf(mB, rmaxB);
        float cA = __expf(mA - mnA),  cB = __expf(mB - mnB);
        float sumA = 0.0f, sumB = 0.0f;

        uint32_t pa[8][4];
#pragma unroll
        for (int s = 0; s < 8; s++) {
            float p0 = __expf(sacc[2 * s][0] - mnA);
            float p1 = __expf(sacc[2 * s][1] - mnA);
            float p2 = __expf(sacc[2 * s][2] - mnB);
            float p3 = __expf(sacc[2 * s][3] - mnB);
            float p4 = __expf(sacc[2 * s + 1][0] - mnA);
            float p5 = __expf(sacc[2 * s + 1][1] - mnA);
            float p6 = __expf(sacc[2 * s + 1][2] - mnB);
            float p7 = __expf(sacc[2 * s + 1][3] - mnB);
            sumA += p0 + p1 + p4 + p5;
            sumB += p2 + p3 + p6 + p7;
            pa[s][0] = pack_h2(p0, p1);
            pa[s][1] = pack_h2(p2, p3);
            pa[s][2] = pack_h2(p4, p5);
            pa[s][3] = pack_h2(p6, p7);
        }
        sumA += __shfl_xor_sync(0xffffffffu, sumA, 1);
        sumA += __shfl_xor_sync(0xffffffffu, sumA, 2);
        sumB += __shfl_xor_sync(0xffffffffu, sumB, 1);
        sumB += __shfl_xor_sync(0xffffffffu, sumB, 2);

        lA = lA * cA + sumA;  lB = lB * cB + sumB;
        mA = mnA;             mB = mnB;
#pragma unroll
        for (int dn = 0; dn < 8; dn++) {
            oacc[dn][0] *= cA; oacc[dn][1] *= cA;
            oacc[dn][2] *= cB; oacc[dn][3] *= cB;
        }

        // O += P @ V
#pragma unroll
        for (int s = 0; s < 8; s++) {
#pragma unroll
            for (int dn = 0; dn < 8; dn++) {
                const __half* vb = &Vh[(dn * 8 + lq) * VH_STRIDE + s * 16 + 2 * lr];
                uint32_t b0 = *(const uint32_t*)vb;
                uint32_t b1 = *(const uint32_t*)(vb + 8);
                mma_f16(oacc[dn], pa[s], b0, b1);
            }
        }
    }

    // normalize + write half to g_Oh [bt][dim]
    const int head = bh & 15;
    float invA = 1.0f / lA, invB = 1.0f / lB;
    size_t rowA = (size_t)(bb * TLEN + q0 + lq) * DIM_ + head * 64;
    size_t rowB = (size_t)(bb * TLEN + q0 + lq + 8) * DIM_ + head * 64;
#pragma unroll
    for (int dn = 0; dn < 8; dn++) {
        *(__half2*)&g_Oh[rowA + dn * 8 + 2 * lr] =
            __floats2half2_rn(oacc[dn][0] * invA, oacc[dn][1] * invA);
        *(__half2*)&g_Oh[rowB + dn * 8 + 2 * lr] =
            __floats2half2_rn(oacc[dn][2] * invB, oacc[dn][3] * invB);
    }
}

// ---------------------------------------------------------------------------
// Kernel 3: output projection fp16 mma + fused residual.
// A = g_Oh [bt][dim] (already half), B = Wo (fp32 -> half).
// ---------------------------------------------------------------------------
__global__ __launch_bounds__(256, 2) void oproj_f16(
    const float* __restrict__ x,
    const float* __restrict__ Wo)
{
    __shared__ __half As[128][SMS];
    __shared__ __half Bs[128][SMS];

    const int tid  = threadIdx.x;
    const int lane = tid & 31;
    const int wid  = tid >> 5;
    const int lq   = lane >> 2;
    const int lr   = lane & 3;
    const int wm   = (wid & 3) * 32;
    const int wn   = (wid >> 2) * 64;
    const int m0   = blockIdx.x * 128;
    const int n0   = blockIdx.y * 128;

    const int lrow = tid >> 3;
    const int lk   = (tid & 7) * 4;

    float acc[2][8][4];
#pragma unroll
    for (int i = 0; i < 2; i++)
#pragma unroll
        for (int j = 0; j < 8; j++)
#pragma unroll
            for (int v = 0; v < 4; v++) acc[i][j][v] = 0.0f;

    for (int k0 = 0; k0 < DIM_; k0 += 32) {
        uint4 lav[2];
        uint32_t lb[4][2];
#pragma unroll
        for (int i = 0; i < 2; i++) {
            int chunk = tid + i * 256;          // 0..511
            int row = chunk >> 2;               // 0..127
            int c8  = (chunk & 3) * 8;
            lav[i] = *(const uint4*)(g_Oh + (size_t)(m0 + row) * DIM_ + k0 + c8);
        }
#pragma unroll
        for (int r = 0; r < 4; r++) {
            float4 vb = *(const float4*)(Wo + (size_t)(n0 + lrow + 32 * r) * DIM_ + k0 + lk);
            lb[r][0] = pack_h2(vb.x, vb.y);
            lb[r][1] = pack_h2(vb.z, vb.w);
        }
        __syncthreads();
#pragma unroll
        for (int i = 0; i < 2; i++) {
            int chunk = tid + i * 256;
            int row = chunk >> 2;
            int c8  = (chunk & 3) * 8;
            *(uint4*)&As[row][c8] = lav[i];
        }
#pragma unroll
        for (int r = 0; r < 4; r++)
            *(uint2*)&Bs[lrow + 32 * r][lk] = make_uint2(lb[r][0], lb[r][1]);
        __syncthreads();

#pragma unroll
        for (int ks = 0; ks < 32; ks += 16) {
            uint32_t a[2][4];
#pragma unroll
            for (int i = 0; i < 2; i++) {
                a[i][0] = *(const uint32_t*)&As[wm + i * 16 + lq][ks + 2 * lr];
                a[i][1] = *(const uint32_t*)&As[wm + i * 16 + 8 + lq][ks + 2 * lr];
                a[i][2] = *(const uint32_t*)&As[wm + i * 16 + lq][ks + 2 * lr + 8];
                a[i][3] = *(const uint32_t*)&As[wm + i * 16 + 8 + lq][ks + 2 * lr + 8];
            }
#pragma unroll
            for (int j = 0; j < 8; j++) {
                uint32_t b0 = *(const uint32_t*)&Bs[wn + j * 8 + lq][ks + 2 * lr];
                uint32_t b1 = *(const uint32_t*)&Bs[wn + j * 8 + lq][ks + 2 * lr + 8];
#pragma unroll
                for (int i = 0; i < 2; i++)
                    mma_f16(acc[i][j], a[i], b0, b1);
            }
        }
        __syncthreads();
    }

    // Epilogue: h = x + proj -> g_Hh
#pragma unroll
    for (int i = 0; i < 2; i++) {
#pragma unroll
        for (int half_ = 0; half_ < 2; half_++) {
            int row = m0 + wm + i * 16 + lq + 8 * half_;
#pragma unroll
            for (int j = 0; j < 8; j++) {
                int ncol = n0 + wn + j * 8 + 2 * lr;
                size_t idx = (size_t)row * DIM_ + ncol;
                float2 xr = *(const float2*)(x + idx);
                *(float2*)(g_Hh + idx) =
                    make_float2(acc[i][j][2 * half_] + xr.x,
                                acc[i][j][2 * half_ + 1] + xr.y);
            }
        }
    }
}

// ---------------------------------------------------------------------------
// Kernel 4: LayerNorm per row of h.
// ---------------------------------------------------------------------------
__global__ __launch_bounds__(256) void ln_kernel(
    const float* __restrict__ gamma,
    const float* __restrict__ beta,
    float* __restrict__ out)
{
    __shared__ float red0[8];
    __shared__ float red1[8];
    const int row = blockIdx.x;
    const int tid = threadIdx.x;
    const float* hr = g_Hh + (size_t)row * DIM_;

    float4 v = *(const float4*)(hr + tid * 4);
    float sum = v.x + v.y + v.z + v.w;
    float sq  = v.x * v.x + v.y * v.y + v.z * v.z + v.w * v.w;
#pragma unroll
    for (int off = 16; off; off >>= 1) {
        sum += __shfl_xor_sync(0xffffffffu, sum, off);
        sq  += __shfl_xor_sync(0xffffffffu, sq, off);
    }
    int wid = tid >> 5, lane = tid & 31;
    if (lane == 0) { red0[wid] = sum; red1[wid] = sq; }
    __syncthreads();

    float tot = 0.0f, totsq = 0.0f;
#pragma unroll
    for (int w = 0; w < 8; w++) { tot += red0[w]; totsq += red1[w]; }

    float mu = tot * (1.0f / DIM_);
    float var = totsq * (1.0f / DIM_) - mu * mu;
    float rs = rsqrtf(var + 1e-5f);

    int e = tid * 4;
    float4 g  = *(const float4*)(gamma + e);
    float4 be = *(const float4*)(beta + e);
    float4 r = make_float4((v.x - mu) * rs * g.x + be.x,
                           (v.y - mu) * rs * g.y + be.y,
                           (v.z - mu) * rs * g.z + be.z,
                           (v.w - mu) * rs * g.w + be.w);
    *(float4*)(out + (size_t)row * DIM_ + e) = r;
}

// ---------------------------------------------------------------------------
extern "C" void kernel_launch(void* const* d_in, const int* in_sizes, int n_in,
                              void* d_out, int out_size)
{
    const float* x     = (const float*)d_in[0];
    const int*   mask  = (const int*)d_in[1];
    const float* Wq    = (const float*)d_in[2];
    const float* Wk    = (const float*)d_in[3];
    const float* Wv    = (const float*)d_in[4];
    const float* Wo    = (const float*)d_in[5];
    const float* gamma = (const float*)d_in[6];
    const float* beta  = (const float*)d_in[7];
    float* out = (float*)d_out;

    cudaFuncSetAttribute(attn_mma,
                         cudaFuncAttributeMaxDynamicSharedMemorySize, ATTN_SMEM);

    qkv_f16<<<dim3(BT / 128, DIM_ / 128, 3), 256>>>(x, Wq, Wk, Wv);

    attn_mma<<<dim3(TLEN / 128, BSZ * NH), 256, ATTN_SMEM>>>(mask);

    oproj_f16<<<dim3(BT / 128, DIM_ / 128), 256>>>(x, Wo);

    ln_kernel<<<BT, 256>>>(gamma, beta, out);
}

// round 8
// speedup vs baseline: 5.3085x; 1.0720x over previous
#include <cuda_runtime.h>
#include <cuda_fp16.h>
#include <math.h>
#include <stddef.h>
#include <stdint.h>

#define BSZ   4
#define TLEN  2048
#define DIM_  1024
#define NH    16
#define HDIM  64
#define BT    (BSZ * TLEN)        // 8192

// Scratch (device-global; no runtime allocation)
__device__ __half g_Qh[(size_t)BSZ * NH * TLEN * HDIM];   // [bh][t][d], rope+scale applied
__device__ __half g_Kh[(size_t)BSZ * NH * TLEN * HDIM];   // [bh][t][d], rope applied
__device__ __half g_Vh[(size_t)BSZ * NH * HDIM * TLEN];   // [bh][d][t]
__device__ __half g_Oh[(size_t)BT * DIM_];                // [bt][dim] attention out
__device__ float  g_Hh[(size_t)BT * DIM_];                // residual sum

// ---------------------------------------------------------------------------
// helpers
// ---------------------------------------------------------------------------
__device__ __forceinline__ void mma_f16(float c[4],
                                        const uint32_t a[4],
                                        uint32_t b0, uint32_t b1) {
    asm volatile(
        "mma.sync.aligned.m16n8k16.row.col.f32.f16.f16.f32 "
        "{%0,%1,%2,%3},{%4,%5,%6,%7},{%8,%9},{%0,%1,%2,%3};"
        : "+f"(c[0]), "+f"(c[1]), "+f"(c[2]), "+f"(c[3])
        : "r"(a[0]), "r"(a[1]), "r"(a[2]), "r"(a[3]),
          "r"(b0), "r"(b1));
}

__device__ __forceinline__ uint32_t pack_h2(float lo, float hi) {
    __half2 h = __floats2half2_rn(lo, hi);
    return *(uint32_t*)&h;
}

__device__ __forceinline__ void cp16(uint32_t dst_smem, const void* src) {
    asm volatile("cp.async.cg.shared.global [%0], [%1], 16;"
                 :: "r"(dst_smem), "l"(src));
}
#define CP_COMMIT() asm volatile("cp.async.commit_group;" ::: "memory")
#define CP_WAIT(n)  asm volatile("cp.async.wait_group %0;" :: "n"(n) : "memory")

#define SMS 72   // smem row stride in halves (conflict-free frags)

// ---------------------------------------------------------------------------
// Kernel 1: QKV projection, fp16 mma, RoPE fused, register-prefetch pipeline.
// CTA 128x128x32, 8 warps of 32x64.
// ---------------------------------------------------------------------------
__global__ __launch_bounds__(256, 2) void qkv_f16(
    const float* __restrict__ x,
    const float* __restrict__ Wq,
    const float* __restrict__ Wk,
    const float* __restrict__ Wv)
{
    __shared__ __half As[128][SMS];
    __shared__ __half Bs[128][SMS];

    const int tid  = threadIdx.x;
    const int lane = tid & 31;
    const int wid  = tid >> 5;
    const int lq   = lane >> 2;
    const int lr   = lane & 3;
    const int wm   = (wid & 3) * 32;
    const int wn   = (wid >> 2) * 64;
    const int m0   = blockIdx.x * 128;
    const int n0   = blockIdx.y * 128;
    const int z    = blockIdx.z;

    const float* __restrict__ W = (z == 0) ? Wq : (z == 1 ? Wk : Wv);

    const int lrow = tid >> 3;
    const int lk   = (tid & 7) * 4;

    float acc[2][8][4];
#pragma unroll
    for (int i = 0; i < 2; i++)
#pragma unroll
        for (int j = 0; j < 8; j++)
#pragma unroll
            for (int v = 0; v < 4; v++) acc[i][j][v] = 0.0f;

    uint32_t la[4][2], lb[4][2];
    // prologue: load k0=0 tile into registers
#pragma unroll
    for (int r = 0; r < 4; r++) {
        float4 va = *(const float4*)(x + (size_t)(m0 + lrow + 32 * r) * DIM_ + lk);
        la[r][0] = pack_h2(va.x, va.y);  la[r][1] = pack_h2(va.z, va.w);
        float4 vb = *(const float4*)(W + (size_t)(n0 + lrow + 32 * r) * DIM_ + lk);
        lb[r][0] = pack_h2(vb.x, vb.y);  lb[r][1] = pack_h2(vb.z, vb.w);
    }

    for (int k0 = 0; k0 < DIM_; k0 += 32) {
        __syncthreads();   // previous mma done reading smem
#pragma unroll
        for (int r = 0; r < 4; r++) {
            *(uint2*)&As[lrow + 32 * r][lk] = make_uint2(la[r][0], la[r][1]);
            *(uint2*)&Bs[lrow + 32 * r][lk] = make_uint2(lb[r][0], lb[r][1]);
        }
        __syncthreads();

        // issue next tile's global loads (overlap with mma below)
        if (k0 + 32 < DIM_) {
            int kn = k0 + 32;
#pragma unroll
            for (int r = 0; r < 4; r++) {
                float4 va = *(const float4*)(x + (size_t)(m0 + lrow + 32 * r) * DIM_ + kn + lk);
                la[r][0] = pack_h2(va.x, va.y);  la[r][1] = pack_h2(va.z, va.w);
                float4 vb = *(const float4*)(W + (size_t)(n0 + lrow + 32 * r) * DIM_ + kn + lk);
                lb[r][0] = pack_h2(vb.x, vb.y);  lb[r][1] = pack_h2(vb.z, vb.w);
            }
        }

#pragma unroll
        for (int ks = 0; ks < 32; ks += 16) {
            uint32_t a[2][4];
#pragma unroll
            for (int i = 0; i < 2; i++) {
                a[i][0] = *(const uint32_t*)&As[wm + i * 16 + lq][ks + 2 * lr];
                a[i][1] = *(const uint32_t*)&As[wm + i * 16 + 8 + lq][ks + 2 * lr];
                a[i][2] = *(const uint32_t*)&As[wm + i * 16 + lq][ks + 2 * lr + 8];
                a[i][3] = *(const uint32_t*)&As[wm + i * 16 + 8 + lq][ks + 2 * lr + 8];
            }
#pragma unroll
            for (int j = 0; j < 8; j++) {
                uint32_t b0 = *(const uint32_t*)&Bs[wn + j * 8 + lq][ks + 2 * lr];
                uint32_t b1 = *(const uint32_t*)&Bs[wn + j * 8 + lq][ks + 2 * lr + 8];
#pragma unroll
                for (int i = 0; i < 2; i++)
                    mma_f16(acc[i][j], a[i], b0, b1);
            }
        }
    }

    // ---- Epilogue ----
    if (z < 2) {
        const float C32 = 13.287712379549449f / 32.0f;
        float fr[4][2];
#pragma unroll
        for (int jl = 0; jl < 4; jl++) {
            fr[jl][0] = exp2f(-(float)(jl * 8 + 2 * lr) * C32);
            fr[jl][1] = exp2f(-(float)(jl * 8 + 2 * lr + 1) * C32);
        }
        const float qs = (z == 0) ? 0.125f : 1.0f;
        __half* __restrict__ outp = (z == 0) ? g_Qh : g_Kh;

#pragma unroll
        for (int i = 0; i < 2; i++) {
#pragma unroll
            for (int half_ = 0; half_ < 2; half_++) {
                int row = m0 + wm + i * 16 + lq + 8 * half_;
                int bb = row >> 11;
                int t  = row & (TLEN - 1);
                float tf = (float)t;
#pragma unroll
                for (int jl = 0; jl < 4; jl++) {
                    int ncol = n0 + wn + jl * 8 + 2 * lr;
                    int head = ncol >> 6;
                    int hd1  = ncol & 63;
                    float o1[2], o2[2];
#pragma unroll
                    for (int v = 0; v < 2; v++) {
                        float s, c;
                        sincosf(tf * fr[jl][v], &s, &c);
                        float q1 = acc[i][jl][2 * half_ + v];
                        float q2 = acc[i][jl + 4][2 * half_ + v];
                        o1[v] = (q1 * c - q2 * s) * qs;
                        o2[v] = (q2 * c + q1 * s) * qs;
                    }
                    size_t base = (((size_t)(bb * NH + head)) * TLEN + t) * HDIM;
                    *(__half2*)&outp[base + hd1] = __floats2half2_rn(o1[0], o1[1]);
                    *(__half2*)&outp[base + hd1 + 32] = __floats2half2_rn(o2[0], o2[1]);
                }
            }
        }
    } else {
#pragma unroll
        for (int i = 0; i < 2; i++) {
#pragma unroll
            for (int half_ = 0; half_ < 2; half_++) {
                int row = m0 + wm + i * 16 + lq + 8 * half_;
                int bb = row >> 11;
                int t  = row & (TLEN - 1);
#pragma unroll
                for (int j = 0; j < 8; j++) {
                    int ncol = n0 + wn + j * 8 + 2 * lr;
                    int head = ncol >> 6;
                    int hd   = ncol & 63;
                    size_t base = ((size_t)(bb * NH + head) * HDIM + hd) * TLEN + t;
                    g_Vh[base]        = __float2half(acc[i][j][2 * half_]);
                    g_Vh[base + TLEN] = __float2half(acc[i][j][2 * half_ + 1]);
                }
            }
        }
    }
}

// ---------------------------------------------------------------------------
// Kernel 2: flash attention, fp16 mma, cp.async double-buffered K/V tiles.
// ---------------------------------------------------------------------------
#define VH_STRIDE 136
#define KBUF_H  (128 * SMS)          // halves per K buffer
#define VBUF_H  (64 * VH_STRIDE)     // halves per V buffer
#define ATTN_SMEM (2 * KBUF_H * 2 + 2 * VBUF_H * 2 + TLEN * 4)

__global__ __launch_bounds__(256) void attn_mma(const int* __restrict__ mask)
{
    extern __shared__ char smraw[];
    __half* Ks0  = (__half*)smraw;
    __half* Vh0  = (__half*)(smraw + 2 * KBUF_H * 2);
    float*  madds = (float*)(smraw + 2 * KBUF_H * 2 + 2 * VBUF_H * 2);

    const int tid  = threadIdx.x;
    const int lane = tid & 31;
    const int wid  = tid >> 5;
    const int lq   = lane >> 2;
    const int lr   = lane & 3;
    const int qt   = blockIdx.x;
    const int bh   = blockIdx.y;
    const int bb   = bh >> 4;
    const int q0   = qt * 128 + wid * 16;

    const __half* __restrict__ Qg = g_Qh + ((size_t)bh * TLEN + q0) * HDIM;
    const __half* __restrict__ Kg = g_Kh + (size_t)bh * TLEN * HDIM;
    const __half* __restrict__ Vg = g_Vh + (size_t)bh * HDIM * TLEN;
    const int*    __restrict__ mrow = mask + (size_t)bb * TLEN;

    const uint32_t ks_base = (uint32_t)__cvta_generic_to_shared(Ks0);
    const uint32_t vh_base = (uint32_t)__cvta_generic_to_shared(Vh0);

    // full-sequence additive mask, computed once
#pragma unroll
    for (int i = 0; i < TLEN / 256; i++)
        madds[tid + i * 256] = (1.0f - (float)mrow[tid + i * 256]) * 1e9f;

    // Q fragments, resident
    uint32_t aq[4][4];
#pragma unroll
    for (int ks = 0; ks < 4; ks++) {
        aq[ks][0] = *(const uint32_t*)&Qg[lq * 64 + ks * 16 + 2 * lr];
        aq[ks][1] = *(const uint32_t*)&Qg[(lq + 8) * 64 + ks * 16 + 2 * lr];
        aq[ks][2] = *(const uint32_t*)&Qg[lq * 64 + ks * 16 + 2 * lr + 8];
        aq[ks][3] = *(const uint32_t*)&Qg[(lq + 8) * 64 + ks * 16 + 2 * lr + 8];
    }

    // tile loader via cp.async (16B per op)
    auto issue_tile = [&](int kt, int buf) {
        uint32_t kdst = ks_base + buf * KBUF_H * 2;
        uint32_t vdst = vh_base + buf * VBUF_H * 2;
#pragma unroll
        for (int i = 0; i < 4; i++) {
            int chunk = tid + i * 256;
            int row = chunk >> 3;
            int c8  = (chunk & 7) * 8;
            cp16(kdst + (row * SMS + c8) * 2,
                 Kg + ((size_t)kt * 128 + row) * 64 + c8);
        }
#pragma unroll
        for (int i = 0; i < 4; i++) {
            int linear = tid + i * 256;
            int d  = linear >> 4;
            int kp = (linear & 15) * 8;
            cp16(vdst + (d * VH_STRIDE + kp) * 2,
                 Vg + (size_t)d * TLEN + kt * 128 + kp);
        }
    };

    float oacc[8][4];
#pragma unroll
    for (int dn = 0; dn < 8; dn++)
#pragma unroll
        for (int v = 0; v < 4; v++) oacc[dn][v] = 0.0f;
    float mA = -1e30f, mB = -1e30f, lA = 0.0f, lB = 0.0f;

    issue_tile(0, 0);
    CP_COMMIT();

    for (int kt = 0; kt < 16; kt++) {
        const int cur = kt & 1;
        if (kt + 1 < 16) {
            issue_tile(kt + 1, cur ^ 1);
            CP_COMMIT();
            CP_WAIT(1);
        } else {
            CP_WAIT(0);
        }
        __syncthreads();   // tile kt visible to all warps

        const __half* Kb = Ks0 + cur * KBUF_H;
        const __half* Vb = Vh0 + cur * VBUF_H;

        // S = Q K^T
        float sacc[16][4];
#pragma unroll
        for (int j = 0; j < 16; j++)
#pragma unroll
            for (int v = 0; v < 4; v++) sacc[j][v] = 0.0f;

#pragma unroll
        for (int j = 0; j < 16; j++) {
#pragma unroll
            for (int ks = 0; ks < 4; ks++) {
                uint32_t b0 = *(const uint32_t*)&Kb[(j * 8 + lq) * SMS + ks * 16 + 2 * lr];
                uint32_t b1 = *(const uint32_t*)&Kb[(j * 8 + lq) * SMS + ks * 16 + 2 * lr + 8];
                mma_f16(sacc[j], aq[ks], b0, b1);
            }
        }

        // mask + online softmax
        const float* mk = madds + kt * 128;
        float rmaxA = -1e30f, rmaxB = -1e30f;
#pragma unroll
        for (int j = 0; j < 16; j++) {
            float m0v = mk[j * 8 + 2 * lr];
            float m1v = mk[j * 8 + 2 * lr + 1];
            sacc[j][0] -= m0v; sacc[j][1] -= m1v;
            sacc[j][2] -= m0v; sacc[j][3] -= m1v;
            rmaxA = fmaxf(rmaxA, fmaxf(sacc[j][0], sacc[j][1]));
            rmaxB = fmaxf(rmaxB, fmaxf(sacc[j][2], sacc[j][3]));
        }
        rmaxA = fmaxf(rmaxA, __shfl_xor_sync(0xffffffffu, rmaxA, 1));
        rmaxA = fmaxf(rmaxA, __shfl_xor_sync(0xffffffffu, rmaxA, 2));
        rmaxB = fmaxf(rmaxB, __shfl_xor_sync(0xffffffffu, rmaxB, 1));
        rmaxB = fmaxf(rmaxB, __shfl_xor_sync(0xffffffffu, rmaxB, 2));

        float mnA = fmaxf(mA, rmaxA), mnB = fmaxf(mB, rmaxB);
        float cA = __expf(mA - mnA),  cB = __expf(mB - mnB);
        float sumA = 0.0f, sumB = 0.0f;

        uint32_t pa[8][4];
#pragma unroll
        for (int s = 0; s < 8; s++) {
            float p0 = __expf(sacc[2 * s][0] - mnA);
            float p1 = __expf(sacc[2 * s][1] - mnA);
            float p2 = __expf(sacc[2 * s][2] - mnB);
            float p3 = __expf(sacc[2 * s][3] - mnB);
            float p4 = __expf(sacc[2 * s + 1][0] - mnA);
            float p5 = __expf(sacc[2 * s + 1][1] - mnA);
            float p6 = __expf(sacc[2 * s + 1][2] - mnB);
            float p7 = __expf(sacc[2 * s + 1][3] - mnB);
            sumA += p0 + p1 + p4 + p5;
            sumB += p2 + p3 + p6 + p7;
            pa[s][0] = pack_h2(p0, p1);
            pa[s][1] = pack_h2(p2, p3);
            pa[s][2] = pack_h2(p4, p5);
            pa[s][3] = pack_h2(p6, p7);
        }
        sumA += __shfl_xor_sync(0xffffffffu, sumA, 1);
        sumA += __shfl_xor_sync(0xffffffffu, sumA, 2);
        sumB += __shfl_xor_sync(0xffffffffu, sumB, 1);
        sumB += __shfl_xor_sync(0xffffffffu, sumB, 2);

        lA = lA * cA + sumA;  lB = lB * cB + sumB;
        mA = mnA;             mB = mnB;
#pragma unroll
        for (int dn = 0; dn < 8; dn++) {
            oacc[dn][0] *= cA; oacc[dn][1] *= cA;
            oacc[dn][2] *= cB; oacc[dn][3] *= cB;
        }

        // O += P @ V
#pragma unroll
        for (int s = 0; s < 8; s++) {
#pragma unroll
            for (int dn = 0; dn < 8; dn++) {
                const __half* vb = &Vb[(dn * 8 + lq) * VH_STRIDE + s * 16 + 2 * lr];
                uint32_t b0 = *(const uint32_t*)vb;
                uint32_t b1 = *(const uint32_t*)(vb + 8);
                mma_f16(oacc[dn], pa[s], b0, b1);
            }
        }
        __syncthreads();   // all warps done with buffer cur before it is refilled
    }

    // normalize + write half to g_Oh [bt][dim]
    const int head = bh & 15;
    float invA = 1.0f / lA, invB = 1.0f / lB;
    size_t rowA = (size_t)(bb * TLEN + q0 + lq) * DIM_ + head * 64;
    size_t rowB = (size_t)(bb * TLEN + q0 + lq + 8) * DIM_ + head * 64;
#pragma unroll
    for (int dn = 0; dn < 8; dn++) {
        *(__half2*)&g_Oh[rowA + dn * 8 + 2 * lr] =
            __floats2half2_rn(oacc[dn][0] * invA, oacc[dn][1] * invA);
        *(__half2*)&g_Oh[rowB + dn * 8 + 2 * lr] =
            __floats2half2_rn(oacc[dn][2] * invB, oacc[dn][3] * invB);
    }
}

// ---------------------------------------------------------------------------
// Kernel 3: output projection fp16 mma + fused residual, register pipeline.
// ---------------------------------------------------------------------------
__global__ __launch_bounds__(256, 2) void oproj_f16(
    const float* __restrict__ x,
    const float* __restrict__ Wo)
{
    __shared__ __half As[128][SMS];
    __shared__ __half Bs[128][SMS];

    const int tid  = threadIdx.x;
    const int lane = tid & 31;
    const int wid  = tid >> 5;
    const int lq   = lane >> 2;
    const int lr   = lane & 3;
    const int wm   = (wid & 3) * 32;
    const int wn   = (wid >> 2) * 64;
    const int m0   = blockIdx.x * 128;
    const int n0   = blockIdx.y * 128;

    const int lrow = tid >> 3;
    const int lk   = (tid & 7) * 4;

    float acc[2][8][4];
#pragma unroll
    for (int i = 0; i < 2; i++)
#pragma unroll
        for (int j = 0; j < 8; j++)
#pragma unroll
            for (int v = 0; v < 4; v++) acc[i][j][v] = 0.0f;

    uint4 lav[2];
    uint32_t lb[4][2];
    // prologue loads (k0 = 0)
#pragma unroll
    for (int i = 0; i < 2; i++) {
        int chunk = tid + i * 256;
        int row = chunk >> 2;
        int c8  = (chunk & 3) * 8;
        lav[i] = *(const uint4*)(g_Oh + (size_t)(m0 + row) * DIM_ + c8);
    }
#pragma unroll
    for (int r = 0; r < 4; r++) {
        float4 vb = *(const float4*)(Wo + (size_t)(n0 + lrow + 32 * r) * DIM_ + lk);
        lb[r][0] = pack_h2(vb.x, vb.y);  lb[r][1] = pack_h2(vb.z, vb.w);
    }

    for (int k0 = 0; k0 < DIM_; k0 += 32) {
        __syncthreads();
#pragma unroll
        for (int i = 0; i < 2; i++) {
            int chunk = tid + i * 256;
            int row = chunk >> 2;
            int c8  = (chunk & 3) * 8;
            *(uint4*)&As[row][c8] = lav[i];
        }
#pragma unroll
        for (int r = 0; r < 4; r++)
            *(uint2*)&Bs[lrow + 32 * r][lk] = make_uint2(lb[r][0], lb[r][1]);
        __syncthreads();

        if (k0 + 32 < DIM_) {
            int kn = k0 + 32;
#pragma unroll
            for (int i = 0; i < 2; i++) {
                int chunk = tid + i * 256;
                int row = chunk >> 2;
                int c8  = (chunk & 3) * 8;
                lav[i] = *(const uint4*)(g_Oh + (size_t)(m0 + row) * DIM_ + kn + c8);
            }
#pragma unroll
            for (int r = 0; r < 4; r++) {
                float4 vb = *(const float4*)(Wo + (size_t)(n0 + lrow + 32 * r) * DIM_ + kn + lk);
                lb[r][0] = pack_h2(vb.x, vb.y);  lb[r][1] = pack_h2(vb.z, vb.w);
            }
        }

#pragma unroll
        for (int ks = 0; ks < 32; ks += 16) {
            uint32_t a[2][4];
#pragma unroll
            for (int i = 0; i < 2; i++) {
                a[i][0] = *(const uint32_t*)&As[wm + i * 16 + lq][ks + 2 * lr];
                a[i][1] = *(const uint32_t*)&As[wm + i * 16 + 8 + lq][ks + 2 * lr];
                a[i][2] = *(const uint32_t*)&As[wm + i * 16 + lq][ks + 2 * lr + 8];
                a[i][3] = *(const uint32_t*)&As[wm + i * 16 + 8 + lq][ks + 2 * lr + 8];
            }
#pragma unroll
            for (int j = 0; j < 8; j++) {
                uint32_t b0 = *(const uint32_t*)&Bs[wn + j * 8 + lq][ks + 2 * lr];
                uint32_t b1 = *(const uint32_t*)&Bs[wn + j * 8 + lq][ks + 2 * lr + 8];
#pragma unroll
                for (int i = 0; i < 2; i++)
                    mma_f16(acc[i][j], a[i], b0, b1);
            }
        }
    }

    // Epilogue: h = x + proj -> g_Hh
#pragma unroll
    for (int i = 0; i < 2; i++) {
#pragma unroll
        for (int half_ = 0; half_ < 2; half_++) {
            int row = m0 + wm + i * 16 + lq + 8 * half_;
#pragma unroll
            for (int j = 0; j < 8; j++) {
                int ncol = n0 + wn + j * 8 + 2 * lr;
                size_t idx = (size_t)row * DIM_ + ncol;
                float2 xr = *(const float2*)(x + idx);
                *(float2*)(g_Hh + idx) =
                    make_float2(acc[i][j][2 * half_] + xr.x,
                                acc[i][j][2 * half_ + 1] + xr.y);
            }
        }
    }
}

// ---------------------------------------------------------------------------
// Kernel 4: LayerNorm per row of h.
// ---------------------------------------------------------------------------
__global__ __launch_bounds__(256) void ln_kernel(
    const float* __restrict__ gamma,
    const float* __restrict__ beta,
    float* __restrict__ out)
{
    __shared__ float red0[8];
    __shared__ float red1[8];
    const int row = blockIdx.x;
    const int tid = threadIdx.x;
    const float* hr = g_Hh + (size_t)row * DIM_;

    float4 v = *(const float4*)(hr + tid * 4);
    float sum = v.x + v.y + v.z + v.w;
    float sq  = v.x * v.x + v.y * v.y + v.z * v.z + v.w * v.w;
#pragma unroll
    for (int off = 16; off; off >>= 1) {
        sum += __shfl_xor_sync(0xffffffffu, sum, off);
        sq  += __shfl_xor_sync(0xffffffffu, sq, off);
    }
    int wid = tid >> 5, lane = tid & 31;
    if (lane == 0) { red0[wid] = sum; red1[wid] = sq; }
    __syncthreads();

    float tot = 0.0f, totsq = 0.0f;
#pragma unroll
    for (int w = 0; w < 8; w++) { tot += red0[w]; totsq += red1[w]; }

    float mu = tot * (1.0f / DIM_);
    float var = totsq * (1.0f / DIM_) - mu * mu;
    float rs = rsqrtf(var + 1e-5f);

    int e = tid * 4;
    float4 g  = *(const float4*)(gamma + e);
    float4 be = *(const float4*)(beta + e);
    float4 r = make_float4((v.x - mu) * rs * g.x + be.x,
                           (v.y - mu) * rs * g.y + be.y,
                           (v.z - mu) * rs * g.z + be.z,
                           (v.w - mu) * rs * g.w + be.w);
    *(float4*)(out + (size_t)row * DIM_ + e) = r;
}

// ---------------------------------------------------------------------------
extern "C" void kernel_launch(void* const* d_in, const int* in_sizes, int n_in,
                              void* d_out, int out_size)
{
    const float* x     = (const float*)d_in[0];
    const int*   mask  = (const int*)d_in[1];
    const float* Wq    = (const float*)d_in[2];
    const float* Wk    = (const float*)d_in[3];
    const float* Wv    = (const float*)d_in[4];
    const float* Wo    = (const float*)d_in[5];
    const float* gamma = (const float*)d_in[6];
    const float* beta  = (const float*)d_in[7];
    float* out = (float*)d_out;

    cudaFuncSetAttribute(attn_mma,
                         cudaFuncAttributeMaxDynamicSharedMemorySize, ATTN_SMEM);

    qkv_f16<<<dim3(BT / 128, DIM_ / 128, 3), 256>>>(x, Wq, Wk, Wv);

    attn_mma<<<dim3(TLEN / 128, BSZ * NH), 256, ATTN_SMEM>>>(mask);

    oproj_f16<<<dim3(BT / 128, DIM_ / 128), 256>>>(x, Wo);

    ln_kernel<<<BT, 256>>>(gamma, beta, out);
}